// round 15
// baseline (speedup 1.0000x reference)
#include <cuda_runtime.h>
#include <cuda_bf16.h>
#include <cuda_fp16.h>
#include <math.h>
#include <stdint.h>

// ----------------------------- constants -----------------------------------
#define NSEQ   1024
#define DIM    1024
#define NH     16
#define NKH    4
#define NQH    4
#define DH     64
#define CBS    16
#define STRIDE 16
#define SBS    32
#define NSEL   8
#define NCB    64      // NSEQ/STRIDE
#define NFINE  32      // NCB/2
#define SCALE  0.125f

// ----------------------------- scratch -------------------------------------
__device__ float  g_q   [NH  * NSEQ * DH];
__device__ __half g_kh  [NKH * NSEQ * DH];
__device__ __half g_vh  [NKH * NSEQ * DH];
__device__ float  g_x   [2 * NKH * NCB * 1024];   // [k; v] MLP inputs
__device__ float  g_h   [2 * NKH * NCB * 1024];   // hidden
__device__ float  g_ckf [NKH * 65 * DH];
__device__ float  g_cvf [NKH * 65 * DH];
__device__ int    g_idx [NKH * NSEQ * NSEL];
__device__ float  g_cout[NH * NSEQ * DH];
__device__ float  g_y   [NSEQ * NH * DH];
__device__ float  g_gate[NSEQ * 2 * NH];
__device__ float  g_ct  [NSEQ * 32];
__device__ float  g_st  [NSEQ * 32];
// transposed weights, [N][K/2] packed bf16x2, hi/lo split
__device__ uint32_t g_wqkvTh[1536 * 512];
__device__ uint32_t g_wqkvTl[1536 * 512];
__device__ uint32_t g_kw1Th [1024 * 512];
__device__ uint32_t g_kw1Tl [1024 * 512];
__device__ uint32_t g_vw1Th [1024 * 512];
__device__ uint32_t g_vw1Tl [1024 * 512];
__device__ uint32_t g_outwTh[1024 * 512];
__device__ uint32_t g_outwTl[1024 * 512];

// ----------------------------- helpers --------------------------------------
__device__ __forceinline__ uint32_t packbf(float x, float y) {
    __nv_bfloat162 v;
    v.x = __float2bfloat16_rn(x);
    v.y = __float2bfloat16_rn(y);
    return *reinterpret_cast<uint32_t*>(&v);
}
__device__ __forceinline__ float bfres(float x) {
    return x - __bfloat162float(__float2bfloat16_rn(x));
}
__device__ __forceinline__ void mma_bf16(float* d,
                                         uint32_t a0, uint32_t a1, uint32_t a2, uint32_t a3,
                                         uint32_t b0, uint32_t b1) {
    asm volatile(
        "mma.sync.aligned.m16n8k16.row.col.f32.bf16.bf16.f32 "
        "{%0,%1,%2,%3}, {%4,%5,%6,%7}, {%8,%9}, {%0,%1,%2,%3};"
        : "+f"(d[0]), "+f"(d[1]), "+f"(d[2]), "+f"(d[3])
        : "r"(a0), "r"(a1), "r"(a2), "r"(a3), "r"(b0), "r"(b1));
}

// rope+scatter for one output pair (i = token, n = even qkv column)
__device__ __forceinline__ void qkv_scatter(
    int i, int n, float a, float b,
    const float* __restrict__ ct, const float* __restrict__ st,
    const float* __restrict__ kpos, const float* __restrict__ vpos,
    float* __restrict__ q, __half* __restrict__ kk,
    __half* __restrict__ vv, float* __restrict__ x)
{
    const int d = n & 63;
    if (n < 1280) {
        const int d2 = d >> 1;
        float cs = ct[i * 32 + d2];
        float sn = st[i * 32 + d2];
        float o1 = a * cs - b * sn;
        float o2 = b * cs + a * sn;
        if (n < 1024) {
            int h = n >> 6;
            *(float2*)&q[((size_t)h * NSEQ + i) * DH + d] = make_float2(o1, o2);
        } else {
            int kh = (n - 1024) >> 6;
            *(__half2*)&kk[((size_t)kh * NSEQ + i) * DH + d] = __floats2half2_rn(o1, o2);
            int blk = i >> 4, ci = i & 15;
            int pos = (kh * CBS + ci) * DH + d;
            float* xd = &x[(size_t)(kh * 64 + blk) * 1024 + ci * 64 + d];
            xd[0] = o1 + kpos[pos];
            xd[1] = o2 + kpos[pos + 1];
        }
    } else {
        int kh = (n - 1280) >> 6;
        *(__half2*)&vv[((size_t)kh * NSEQ + i) * DH + d] = __floats2half2_rn(a, b);
        int blk = i >> 4, ci = i & 15;
        int pos = (kh * CBS + ci) * DH + d;
        float* xd = &x[262144 + (size_t)(kh * 64 + blk) * 1024 + ci * 64 + d];
        xd[0] = a + vpos[pos];
        xd[1] = b + vpos[pos + 1];
    }
}

// --------- precision-split bf16 tensor-core GEMM (128x128 CTA tile) ---------
// QKV=1: epilogue fuses rope + q/k/v split + MLP-input build (C unused).
#define TG_RSTRIDE 20
#define TG_TILE_W  (128 * TG_RSTRIDE)
#define TG_BUF_W   (4 * TG_TILE_W)
#define TG_SMEM    (2 * TG_BUF_W * 4)
template<int ACT, int QKV>   // ACT: 0 none, 1 relu
__global__ __launch_bounds__(256)
void tgemm(const float* __restrict__ A,
           const uint32_t* __restrict__ BH0, const uint32_t* __restrict__ BH1,
           const uint32_t* __restrict__ BL0, const uint32_t* __restrict__ BL1,
           const float* __restrict__ bias0, const float* __restrict__ bias1,
           float* __restrict__ C, int Nc, int K, int bsA, int bsC,
           const float* __restrict__ ct, const float* __restrict__ st,
           const float* __restrict__ kpos, const float* __restrict__ vpos,
           float* __restrict__ qout, __half* __restrict__ kkout,
           __half* __restrict__ vvout, float* __restrict__ xout)
{
    extern __shared__ uint32_t smw[];
    const int z = blockIdx.z;
    const uint32_t* BH = z ? BH1 : BH0;
    const uint32_t* BL = z ? BL1 : BL0;
    const float* bias  = z ? bias1 : bias0;
    A += (size_t)z * bsA;
    C += (size_t)z * bsC;
    const int Kw = K >> 1;

    const int tid = threadIdx.x, wid = tid >> 5, lane = tid & 31;
    const int grp = lane >> 2, thr = lane & 3;
    const int wm = wid & 1, wn = wid >> 1;
    const int m0 = blockIdx.y * 128, n0 = blockIdx.x * 128;

    const int r0 = tid >> 3, c4 = tid & 7;
    const float*    Ap  = A  + (size_t)(m0 + r0) * K  + c4 * 4;
    const uint32_t* BHp = BH + (size_t)(n0 + r0) * Kw + c4 * 2;
    const uint32_t* BLp = BL + (size_t)(n0 + r0) * Kw + c4 * 2;

    float acc[4][4][4];
#pragma unroll
    for (int i = 0; i < 4; i++)
#pragma unroll
        for (int j = 0; j < 4; j++)
#pragma unroll
            for (int r = 0; r < 4; r++) acc[i][j][r] = 0.f;

    float4 av[4];
    uint2  bhv[4], blv[4];

#define STAGE(bufbase)                                                        \
    do {                                                                      \
        uint32_t* Ah = smw + (bufbase);                                       \
        uint32_t* Al = Ah + TG_TILE_W;                                        \
        uint32_t* Bh = Ah + 2 * TG_TILE_W;                                    \
        uint32_t* Bl = Ah + 3 * TG_TILE_W;                                    \
        _Pragma("unroll")                                                     \
        for (int j = 0; j < 4; j++) {                                         \
            int ro = (r0 + 32 * j) * TG_RSTRIDE + c4 * 2;                     \
            Ah[ro]     = packbf(av[j].x, av[j].y);                            \
            Ah[ro + 1] = packbf(av[j].z, av[j].w);                            \
            Al[ro]     = packbf(bfres(av[j].x), bfres(av[j].y));              \
            Al[ro + 1] = packbf(bfres(av[j].z), bfres(av[j].w));              \
            Bh[ro] = bhv[j].x; Bh[ro + 1] = bhv[j].y;                         \
            Bl[ro] = blv[j].x; Bl[ro + 1] = blv[j].y;                         \
        }                                                                     \
    } while (0)

#pragma unroll
    for (int j = 0; j < 4; j++) {
        av[j]  = *(const float4*)(Ap + (size_t)(32 * j) * K);
        bhv[j] = *(const uint2*)(BHp + (size_t)(32 * j) * Kw);
        blv[j] = *(const uint2*)(BLp + (size_t)(32 * j) * Kw);
    }
    STAGE(0);
    __syncthreads();

    const int nchunk = K >> 5;
    int cur = 0;
    for (int ch = 0; ch < nchunk; ch++) {
        const bool nxt = (ch + 1) < nchunk;
        if (nxt) {
            const int ko = (ch + 1) * 32, kw = (ch + 1) * 16;
#pragma unroll
            for (int j = 0; j < 4; j++) {
                av[j]  = *(const float4*)(Ap + (size_t)(32 * j) * K + ko);
                bhv[j] = *(const uint2*)(BHp + (size_t)(32 * j) * Kw + kw);
                blv[j] = *(const uint2*)(BLp + (size_t)(32 * j) * Kw + kw);
            }
        }
        const uint32_t* Ah = smw + cur * TG_BUF_W;
        const uint32_t* Al = Ah + TG_TILE_W;
        const uint32_t* Bh = Ah + 2 * TG_TILE_W;
        const uint32_t* Bl = Ah + 3 * TG_TILE_W;
#pragma unroll
        for (int ks = 0; ks < 2; ks++) {
            const int w0 = ks * 8;
            uint32_t ahf[4][4], alf[4][4], bhf[4][2], blf[4][2];
#pragma unroll
            for (int mt = 0; mt < 4; mt++) {
                const uint32_t* ap = Ah + (wm * 64 + mt * 16 + grp) * TG_RSTRIDE + w0 + thr;
                ahf[mt][0] = ap[0];
                ahf[mt][1] = ap[8 * TG_RSTRIDE];
                ahf[mt][2] = ap[4];
                ahf[mt][3] = ap[8 * TG_RSTRIDE + 4];
                const uint32_t* alp = Al + (wm * 64 + mt * 16 + grp) * TG_RSTRIDE + w0 + thr;
                alf[mt][0] = alp[0];
                alf[mt][1] = alp[8 * TG_RSTRIDE];
                alf[mt][2] = alp[4];
                alf[mt][3] = alp[8 * TG_RSTRIDE + 4];
            }
#pragma unroll
            for (int nt = 0; nt < 4; nt++) {
                const uint32_t* bp = Bh + (wn * 32 + nt * 8 + grp) * TG_RSTRIDE + w0 + thr;
                bhf[nt][0] = bp[0];
                bhf[nt][1] = bp[4];
                const uint32_t* blp = Bl + (wn * 32 + nt * 8 + grp) * TG_RSTRIDE + w0 + thr;
                blf[nt][0] = blp[0];
                blf[nt][1] = blp[4];
            }
#pragma unroll
            for (int mt = 0; mt < 4; mt++)
#pragma unroll
                for (int nt = 0; nt < 4; nt++) {
                    mma_bf16(acc[mt][nt], ahf[mt][0], ahf[mt][1], ahf[mt][2], ahf[mt][3],
                             bhf[nt][0], bhf[nt][1]);
                    mma_bf16(acc[mt][nt], ahf[mt][0], ahf[mt][1], ahf[mt][2], ahf[mt][3],
                             blf[nt][0], blf[nt][1]);
                    mma_bf16(acc[mt][nt], alf[mt][0], alf[mt][1], alf[mt][2], alf[mt][3],
                             bhf[nt][0], bhf[nt][1]);
                }
        }
        if (nxt) STAGE((cur ^ 1) * TG_BUF_W);
        __syncthreads();
        cur ^= 1;
    }
#undef STAGE

#pragma unroll
    for (int mt = 0; mt < 4; mt++) {
        const int m = m0 + wm * 64 + mt * 16 + grp;
#pragma unroll
        for (int nt = 0; nt < 4; nt++) {
            const int n = n0 + wn * 32 + nt * 8 + 2 * thr;
            if (QKV) {
                qkv_scatter(m,     n, acc[mt][nt][0], acc[mt][nt][1],
                            ct, st, kpos, vpos, qout, kkout, vvout, xout);
                qkv_scatter(m + 8, n, acc[mt][nt][2], acc[mt][nt][3],
                            ct, st, kpos, vpos, qout, kkout, vvout, xout);
            } else {
                float b0 = 0.f, b1 = 0.f;
                if (bias) { b0 = bias[n]; b1 = bias[n + 1]; }
                float v0 = acc[mt][nt][0] + b0;
                float v1 = acc[mt][nt][1] + b1;
                float v2 = acc[mt][nt][2] + b0;
                float v3 = acc[mt][nt][3] + b1;
                if (ACT == 1) {
                    v0 = fmaxf(v0, 0.f); v1 = fmaxf(v1, 0.f);
                    v2 = fmaxf(v2, 0.f); v3 = fmaxf(v3, 0.f);
                }
                *(float2*)(C + (size_t)m * Nc + n)       = make_float2(v0, v1);
                *(float2*)(C + (size_t)(m + 8) * Nc + n) = make_float2(v2, v3);
            }
        }
    }
}

// --------------- split-K skinny GEMM body (device function) ------------------
// KS-way K-split, RM rows per CTA, NC columns. RM*(NC/4)*KS == 256 threads.
// CKV=1: output row remapped to ckf/cvf layout (row + row/64 + 1).
template<int NC, int ACT, int CKV, int RM, int KS, int CHUNK>
__device__ __forceinline__ void skinny_body(
    const float* __restrict__ A, const float* __restrict__ B,
    const float* __restrict__ bias, float* __restrict__ C,
    int K, int bx, float* sm, int tid)
{
    constexpr int CG  = NC / 4;
    constexpr int TPS = 256 / KS;
    constexpr int AST = CHUNK + 4;
    float* As  = sm;                        // KS*RM*AST
    float* Bs  = As + KS * RM * AST;        // KS*CHUNK*NC
    float* red = Bs + KS * CHUNK * NC;      // KS*RM*NC

    const int ks  = tid / TPS;
    const int t   = tid % TPS;
    const int rr  = t / CG, cg = t % CG;
    const int r0  = bx * RM;
    const int ksl = K / KS;
    const int kbase = ks * ksl;

    float acc[4] = {0.f, 0.f, 0.f, 0.f};

    for (int c = 0; c < ksl; c += CHUNK) {
        for (int l = t; l < RM * (CHUNK / 4); l += TPS) {
            int row = l / (CHUNK / 4), c4 = (l % (CHUNK / 4)) * 4;
            *(float4*)&As[(ks * RM + row) * AST + c4] =
                *(const float4*)(A + (size_t)(r0 + row) * K + kbase + c + c4);
        }
        for (int l = t; l < CHUNK * CG; l += TPS) {
            int row = l / CG, c4 = (l % CG) * 4;
            *(float4*)&Bs[(ks * CHUNK + row) * NC + c4] =
                *(const float4*)(B + (size_t)(kbase + c + row) * NC + c4);
        }
        __syncthreads();
#pragma unroll
        for (int kk = 0; kk < CHUNK; kk++) {
            float a = As[(ks * RM + rr) * AST + kk];
            float4 b = *(const float4*)&Bs[(ks * CHUNK + kk) * NC + cg * 4];
            acc[0] += a * b.x;
            acc[1] += a * b.y;
            acc[2] += a * b.z;
            acc[3] += a * b.w;
        }
        __syncthreads();
    }

    *(float4*)&red[(ks * RM + rr) * NC + cg * 4] =
        make_float4(acc[0], acc[1], acc[2], acc[3]);
    __syncthreads();

    if (ks == 0) {
#pragma unroll
        for (int c4i = 0; c4i < 4; c4i++) {
            int col = cg * 4 + c4i;
            float v = 0.f;
#pragma unroll
            for (int s = 0; s < KS; s++) v += red[(s * RM + rr) * NC + col];
            if (bias) v += bias[col];
            if (ACT == 1) v = fmaxf(v, 0.f);
            if (ACT == 2) v = 1.f / (1.f + __expf(-v));
            int orow = r0 + rr;
            if (CKV) orow = orow + (orow >> 6) + 1;
            C[(size_t)orow * NC + col] = v;
        }
    }
}

// - fused weight transposes + rope table (z==4) + gates GEMM (z==5, hoisted) -
__global__ void transpose_split_all(
    const float* __restrict__ s0, uint32_t* __restrict__ h0, uint32_t* __restrict__ l0,
    const float* __restrict__ s1, uint32_t* __restrict__ h1, uint32_t* __restrict__ l1,
    const float* __restrict__ s2, uint32_t* __restrict__ h2, uint32_t* __restrict__ l2,
    const float* __restrict__ s3, uint32_t* __restrict__ h3, uint32_t* __restrict__ l3,
    float* __restrict__ ct, float* __restrict__ st,
    const float* __restrict__ inp,
    const float* __restrict__ gate_w, const float* __restrict__ gate_b,
    float* __restrict__ gate)
{
    __shared__ float smbuf[6272];   // gates skinny body scratch
    __shared__ float t[32][33];
    const int z = blockIdx.z;
    const int tlin = threadIdx.y * 32 + threadIdx.x;
    if (z == 4) {
        int bidl = blockIdx.y * 48 + blockIdx.x;
        if (bidl >= 128) return;
        int id = bidl * 256 + tlin;
        int i = id >> 5, d2 = id & 31;
        double inv = exp((double)d2 * -0.28782313662425575);  // -ln(10000)/32
        double ang = (double)i * inv;
        double kq  = floor(ang * 0.15915494309189535);        // 1/(2*pi)
        float red  = (float)(ang - kq * 6.283185307179586);
        float sn, cs;
        sincosf(red, &sn, &cs);
        ct[id] = cs;
        st[id] = sn;
        return;
    }
    if (z == 5) {
        // gates: [1024,1024]@[1024,32]+sigmoid, only needs inp (input tensor)
        int bidl = blockIdx.y * 48 + blockIdx.x;
        if (bidl >= 128) return;
        skinny_body<32, 2, 0, 8, 4, 32>(inp, gate_w, gate_b, gate,
                                        1024, bidl, smbuf, tlin);
        return;
    }
    const float* src = (z == 0) ? s0 : (z == 1) ? s1 : (z == 2) ? s2 : s3;
    uint32_t* hi = (z == 0) ? h0 : (z == 1) ? h1 : (z == 2) ? h2 : h3;
    uint32_t* lo = (z == 0) ? l0 : (z == 1) ? l1 : (z == 2) ? l2 : l3;
    const int N = (z == 0) ? 1536 : 1024;
    const int K = 1024;
    if (blockIdx.x * 32 >= N) return;

    const int bx = blockIdx.x * 32, by = blockIdx.y * 32;
    const int tx = threadIdx.x, ty = threadIdx.y;
#pragma unroll
    for (int j = 0; j < 32; j += 8)
        t[ty + j][tx] = src[(size_t)(by + ty + j) * N + bx + tx];
    __syncthreads();
    const int Kw = K >> 1;
    if (tx < 16) {
#pragma unroll
        for (int jj = 0; jj < 4; jj++) {
            int n_l = ty + 8 * jj;
            float x0 = t[2 * tx][n_l];
            float x1 = t[2 * tx + 1][n_l];
            size_t o = (size_t)(bx + n_l) * Kw + (by >> 1) + tx;
            hi[o] = packbf(x0, x1);
            lo[o] = packbf(bfres(x0), bfres(x1));
        }
    }
}

// -------------------- mlp2 (k,v) split-K GEMM, one launch --------------------
// grid (128, 2): y=0 mlp2-k, y=1 mlp2-v
__global__ __launch_bounds__(256)
void skinny_fused(const float* __restrict__ h,
                  const float* __restrict__ kc_w2, const float* __restrict__ vc_w2,
                  const float* __restrict__ kc_b2, const float* __restrict__ vc_b2,
                  float* __restrict__ ckf, float* __restrict__ cvf)
{
    // mlp2 body needs 8*2*20 + 8*16*64 + 8*2*64 = 9536 floats (38144 B)
    __shared__ float sm[9536];
    const int y = blockIdx.y;
    skinny_body<64, 0, 1, 2, 8, 16>(h + (size_t)y * 262144,
                                    y ? vc_w2 : kc_w2,
                                    y ? vc_b2 : kc_b2,
                                    y ? cvf : ckf,
                                    1024, blockIdx.x, sm, threadIdx.x);
}

// ------------------ coarse attention + fused top-k ---------------------------
__global__ __launch_bounds__(256)
void coarse_attn(const float* __restrict__ q, const float* __restrict__ ckf,
                 const float* __restrict__ cvf, const float* __restrict__ memkv,
                 float* __restrict__ cout, int* __restrict__ idx)
{
    __shared__ float s_ck[65 * 65];
    __shared__ float s_cv[65 * 64];
    __shared__ float s_imp[32 * 32];
    const int kh = blockIdx.y;
    const int q0 = blockIdx.x * 32;
    const int tid = threadIdx.x;
    for (int e = tid; e < 65 * 64; e += 256) {
        int j = e >> 6, d = e & 63;
        float ckv, cvv;
        if (j == 0) {
            ckv = memkv[kh * DH + d];
            cvv = memkv[NKH * DH + kh * DH + d];
        } else {
            ckv = ckf[kh * 65 * 64 + e];
            cvv = cvf[kh * 65 * 64 + e];
        }
        s_ck[j * 65 + d] = ckv;
        s_cv[e] = cvv;
    }
    for (int e = tid; e < 32 * 32; e += 256) s_imp[e] = 0.f;
    __syncthreads();

    const int warp = tid >> 5, lane = tid & 31;
    for (int unit = warp; unit < 128; unit += 8) {
        const int ql = unit >> 2;
        const int qh = unit & 3;
        const int qi = q0 + ql;
        const int h  = kh * NQH + qh;
        const float* qp = q + ((size_t)h * NSEQ + qi) * DH;
        const float qa = qp[lane], qb = qp[lane + 32];

        float s0 = 0.f, s1 = 0.f, s2 = 0.f;
#pragma unroll 8
        for (int d = 0; d < 32; d++) {
            float qd = __shfl_sync(0xffffffffu, qa, d);
            s0 += qd * s_ck[lane * 65 + d];
            s1 += qd * s_ck[(lane + 32) * 65 + d];
            s2 += qd * s_ck[64 * 65 + d];
        }
#pragma unroll 8
        for (int d = 0; d < 32; d++) {
            float qd = __shfl_sync(0xffffffffu, qb, d);
            s0 += qd * s_ck[lane * 65 + 32 + d];
            s1 += qd * s_ck[(lane + 32) * 65 + 32 + d];
            s2 += qd * s_ck[64 * 65 + 32 + d];
        }
        s0 *= SCALE; s1 *= SCALE; s2 *= SCALE;

        if (lane >= 1) atomicAdd(&s_imp[ql * 32 + ((lane - 1) >> 1)], s0);
        atomicAdd(&s_imp[ql * 32 + ((lane + 31) >> 1)], s1);
        if (lane == 0) atomicAdd(&s_imp[ql * 32 + 31], s2);

        float m = fmaxf(fmaxf(s0, s1), s2);
#pragma unroll
        for (int off = 16; off; off >>= 1)
            m = fmaxf(m, __shfl_xor_sync(0xffffffffu, m, off));
        float e0 = __expf(s0 - m);
        float e1 = __expf(s1 - m);
        float e2 = __expf(s2 - m);
        float den = e0 + e1;
#pragma unroll
        for (int off = 16; off; off >>= 1)
            den += __shfl_xor_sync(0xffffffffu, den, off);
        den += e2;

        float o0 = 0.f, o1 = 0.f;
#pragma unroll 8
        for (int j = 0; j < 32; j++) {
            float p = __shfl_sync(0xffffffffu, e0, j);
            o0 += p * s_cv[j * 64 + lane];
            o1 += p * s_cv[j * 64 + lane + 32];
        }
#pragma unroll 8
        for (int j = 0; j < 32; j++) {
            float p = __shfl_sync(0xffffffffu, e1, j);
            o0 += p * s_cv[(j + 32) * 64 + lane];
            o1 += p * s_cv[(j + 32) * 64 + lane + 32];
        }
        o0 += e2 * s_cv[64 * 64 + lane];
        o1 += e2 * s_cv[64 * 64 + lane + 32];

        float invd = 1.f / den;
        float* op = cout + ((size_t)h * NSEQ + qi) * DH;
        op[lane]      = o0 * invd;
        op[lane + 32] = o1 * invd;
    }
    __syncthreads();

    // fused top-8 per query (ranking invariant to the /8 scaling)
    for (int ql = warp; ql < 32; ql += 8) {
        float v = s_imp[ql * 32 + lane];
        int* od = idx + ((size_t)kh * NSEQ + q0 + ql) * NSEL;
        for (int s = 0; s < NSEL; s++) {
            float bv = v; int bi = lane;
#pragma unroll
            for (int off = 16; off; off >>= 1) {
                float ov = __shfl_xor_sync(0xffffffffu, bv, off);
                int   oi = __shfl_xor_sync(0xffffffffu, bi, off);
                if (ov > bv || (ov == bv && oi < bi)) { bv = ov; bi = oi; }
            }
            if (lane == 0) od[s] = bi;
            if (lane == bi) v = -INFINITY;
        }
    }
}

// --------- fine attention (fp16 K/V) + fused gated combine ------------------
// V chunk-0 gather issued BEFORE the softmax so its latency overlaps it.
__global__ __launch_bounds__(128)
void fine_attn(const float* __restrict__ q, const __half* __restrict__ kk,
               const __half* __restrict__ vv, const int* __restrict__ idx,
               const float* __restrict__ cout, const float* __restrict__ gate,
               float* __restrict__ y)
{
    __shared__ __half ks[128 * 66];
    __shared__ float qs[4 * 64];
    __shared__ float ssim[4 * 256];
    __shared__ float part[4][4][64];
    __shared__ float sden[4];
    __shared__ int   sidx[8];
    const int i = blockIdx.x, kh = blockIdx.y;
    const int tid = threadIdx.x, w = tid >> 5, lane = tid & 31;

    if (tid < 8) sidx[tid] = idx[((size_t)kh * NSEQ + i) * NSEL + tid];
    for (int t = tid; t < 256; t += 128) {
        int h = t >> 6, d = t & 63;
        qs[t] = q[((size_t)(kh * NQH + h) * NSEQ + i) * DH + d];
    }
    __syncthreads();

    const int row = w * 32 + lane;
    const __half2* ksh2 = (const __half2*)ks;
    const float2*  qs2  = (const float2*)qs;

    // Phase A: logits
    for (int c = 0; c < 2; c++) {
        for (int e = tid; e < 1024; e += 128) {
            int r = e >> 3, d8 = e & 7;
            int blk = sidx[c * 4 + (r >> 5)];
            uint4 kvv = *(const uint4*)&kk[(((size_t)kh * NSEQ) + blk * SBS + (r & 31)) * DH + d8 * 8];
            uint32_t* dst = (uint32_t*)&ks[r * 66 + d8 * 8];
            dst[0] = kvv.x; dst[1] = kvv.y; dst[2] = kvv.z; dst[3] = kvv.w;
        }
        __syncthreads();
        float s[4] = {0.f, 0.f, 0.f, 0.f};
#pragma unroll 4
        for (int d2 = 0; d2 < 32; d2++) {
            float2 kf = __half22float2(ksh2[row * 33 + d2]);
#pragma unroll
            for (int h = 0; h < 4; h++) {
                float2 qf = qs2[h * 32 + d2];
                s[h] += qf.x * kf.x + qf.y * kf.y;
            }
        }
#pragma unroll
        for (int h = 0; h < 4; h++)
            ssim[h * 256 + c * 128 + row] = s[h] * SCALE;
        __syncthreads();
    }

    // prefetch V chunk 0 into ks (free after phase A); softmax overlaps the loads
    for (int e = tid; e < 1024; e += 128) {
        int r = e >> 3, d8 = e & 7;
        int blk = sidx[(r >> 5)];
        uint4 vvv = *(const uint4*)&vv[(((size_t)kh * NSEQ) + blk * SBS + (r & 31)) * DH + d8 * 8];
        uint32_t* dst = (uint32_t*)&ks[r * 66 + d8 * 8];
        dst[0] = vvv.x; dst[1] = vvv.y; dst[2] = vvv.z; dst[3] = vvv.w;
    }

    // softmax: warp w handles head w (reads/writes ssim only — no ks conflict)
    float m = -INFINITY;
    for (int t = lane; t < 256; t += 32) m = fmaxf(m, ssim[w * 256 + t]);
#pragma unroll
    for (int off = 16; off; off >>= 1)
        m = fmaxf(m, __shfl_xor_sync(0xffffffffu, m, off));
    float s = 0.f;
    for (int t = lane; t < 256; t += 32) {
        float e = __expf(ssim[w * 256 + t] - m);
        ssim[w * 256 + t] = e;
        s += e;
    }
#pragma unroll
    for (int off = 16; off; off >>= 1)
        s += __shfl_xor_sync(0xffffffffu, s, off);
    if (lane == 0) sden[w] = s;
    __syncthreads();

    // Phase C: output (V0 already resident; load V1 between chunks)
    float o0[4] = {0.f, 0.f, 0.f, 0.f}, o1[4] = {0.f, 0.f, 0.f, 0.f};
    for (int c = 0; c < 2; c++) {
        if (c == 1) {
            for (int e = tid; e < 1024; e += 128) {
                int r = e >> 3, d8 = e & 7;
                int blk = sidx[4 + (r >> 5)];
                uint4 vvv = *(const uint4*)&vv[(((size_t)kh * NSEQ) + blk * SBS + (r & 31)) * DH + d8 * 8];
                uint32_t* dst = (uint32_t*)&ks[r * 66 + d8 * 8];
                dst[0] = vvv.x; dst[1] = vvv.y; dst[2] = vvv.z; dst[3] = vvv.w;
            }
            __syncthreads();
        }
#pragma unroll 4
        for (int jj = 0; jj < 32; jj++) {
            int r2 = w * 32 + jj;
            float v0 = __half2float(ks[r2 * 66 + lane]);
            float v1 = __half2float(ks[r2 * 66 + lane + 32]);
#pragma unroll
            for (int h = 0; h < 4; h++) {
                float p = ssim[h * 256 + c * 128 + r2];
                o0[h] += p * v0;
                o1[h] += p * v1;
            }
        }
        if (c == 0) __syncthreads();   // before V1 overwrites ks
    }

#pragma unroll
    for (int h = 0; h < 4; h++) {
        part[w][h][lane]      = o0[h];
        part[w][h][lane + 32] = o1[h];
    }
    __syncthreads();
    float r0 = part[0][w][lane] + part[1][w][lane] + part[2][w][lane] + part[3][w][lane];
    float r1 = part[0][w][lane + 32] + part[1][w][lane + 32] +
               part[2][w][lane + 32] + part[3][w][lane + 32];
    float invd = 1.f / sden[w];

    const int h = kh * NQH + w;
    float g0 = gate[i * 32 + 2 * h];
    float g1 = gate[i * 32 + 2 * h + 1];
    const float* cp = cout + ((size_t)h * NSEQ + i) * DH;
    float* op = y + (size_t)i * 1024 + h * 64;
    op[lane]      = g0 * cp[lane]      + g1 * (r0 * invd);
    op[lane + 32] = g0 * cp[lane + 32] + g1 * (r1 * invd);
}

// ----------------------------- launcher -------------------------------------
extern "C" void kernel_launch(void* const* d_in, const int* in_sizes, int n_in,
                              void* d_out, int out_size)
{
    const float* inp    = (const float*)d_in[0];
    const float* w_qkv  = (const float*)d_in[1];
    const float* k_pos  = (const float*)d_in[2];
    const float* v_pos  = (const float*)d_in[3];
    const float* mem_kv = (const float*)d_in[4];
    const float* kc_w1  = (const float*)d_in[5];
    const float* kc_b1  = (const float*)d_in[6];
    const float* kc_w2  = (const float*)d_in[7];
    const float* kc_b2  = (const float*)d_in[8];
    const float* vc_w1  = (const float*)d_in[9];
    const float* vc_b1  = (const float*)d_in[10];
    const float* vc_w2  = (const float*)d_in[11];
    const float* vc_b2  = (const float*)d_in[12];
    const float* gate_w = (const float*)d_in[13];
    const float* gate_b = (const float*)d_in[14];
    const float* out_w  = (const float*)d_in[15];
    float* out = (float*)d_out;

    float *p_q, *p_x, *p_h;
    float *p_ckf, *p_cvf, *p_cout, *p_y, *p_gate, *p_ct, *p_st;
    __half *p_kh, *p_vh;
    uint32_t *p_wqkvTh, *p_wqkvTl, *p_kw1Th, *p_kw1Tl, *p_vw1Th, *p_vw1Tl, *p_outwTh, *p_outwTl;
    int* p_idx;
    cudaGetSymbolAddress((void**)&p_q,    g_q);
    cudaGetSymbolAddress((void**)&p_kh,   g_kh);
    cudaGetSymbolAddress((void**)&p_vh,   g_vh);
    cudaGetSymbolAddress((void**)&p_x,    g_x);
    cudaGetSymbolAddress((void**)&p_h,    g_h);
    cudaGetSymbolAddress((void**)&p_ckf,  g_ckf);
    cudaGetSymbolAddress((void**)&p_cvf,  g_cvf);
    cudaGetSymbolAddress((void**)&p_idx,  g_idx);
    cudaGetSymbolAddress((void**)&p_cout, g_cout);
    cudaGetSymbolAddress((void**)&p_y,    g_y);
    cudaGetSymbolAddress((void**)&p_gate, g_gate);
    cudaGetSymbolAddress((void**)&p_ct,   g_ct);
    cudaGetSymbolAddress((void**)&p_st,   g_st);
    cudaGetSymbolAddress((void**)&p_wqkvTh, g_wqkvTh);
    cudaGetSymbolAddress((void**)&p_wqkvTl, g_wqkvTl);
    cudaGetSymbolAddress((void**)&p_kw1Th,  g_kw1Th);
    cudaGetSymbolAddress((void**)&p_kw1Tl,  g_kw1Tl);
    cudaGetSymbolAddress((void**)&p_vw1Th,  g_vw1Th);
    cudaGetSymbolAddress((void**)&p_vw1Tl,  g_vw1Tl);
    cudaGetSymbolAddress((void**)&p_outwTh, g_outwTh);
    cudaGetSymbolAddress((void**)&p_outwTl, g_outwTl);

    cudaFuncSetAttribute(tgemm<0, 0>, cudaFuncAttributeMaxDynamicSharedMemorySize, TG_SMEM);
    cudaFuncSetAttribute(tgemm<1, 0>, cudaFuncAttributeMaxDynamicSharedMemorySize, TG_SMEM);
    cudaFuncSetAttribute(tgemm<0, 1>, cudaFuncAttributeMaxDynamicSharedMemorySize, TG_SMEM);

    // 0) fused weight transposes + rope table (z==4) + gates GEMM (z==5)
    transpose_split_all<<<dim3(48, 32, 6), dim3(32, 8)>>>(
        w_qkv, p_wqkvTh, p_wqkvTl,
        kc_w1, p_kw1Th,  p_kw1Tl,
        vc_w1, p_vw1Th,  p_vw1Tl,
        out_w, p_outwTh, p_outwTl,
        p_ct, p_st,
        inp, gate_w, gate_b, p_gate);
    // 1) qkv projection with fused rope/split/x-build/fp16 epilogue
    tgemm<0, 1><<<dim3(12, 8, 1), 256, TG_SMEM>>>(
        inp, p_wqkvTh, p_wqkvTh, p_wqkvTl, p_wqkvTl, nullptr, nullptr,
        nullptr, 1536, 1024, 0, 0,
        p_ct, p_st, k_pos, v_pos, p_q, p_kh, p_vh, p_x);
    // 2) MLP layer 1 (relu), batched k/v
    tgemm<1, 0><<<dim3(8, 2, 2), 256, TG_SMEM>>>(
        p_x, p_kw1Th, p_vw1Th, p_kw1Tl, p_vw1Tl, kc_b1, vc_b1,
        p_h, 1024, 1024, 262144, 262144,
        nullptr, nullptr, nullptr, nullptr, nullptr, nullptr, nullptr, nullptr);
    // 3) MLP layer 2 (k,v) split-K, one launch (256 CTAs)
    skinny_fused<<<dim3(128, 2), 256>>>(p_h, kc_w2, vc_w2, kc_b2, vc_b2,
                                        p_ckf, p_cvf);
    // 4) coarse attention + importance + fused top-8
    coarse_attn<<<dim3(32, 4), 256>>>(p_q, p_ckf, p_cvf, mem_kv, p_cout, p_idx);
    // 5) fine attention (fp16 K/V) + fused gated combine -> y
    fine_attn<<<dim3(1024, 4), 128>>>(p_q, p_kh, p_vh, p_idx, p_cout, p_gate, p_y);
    // 6) output projection (bf16 3-term split)
    tgemm<0, 0><<<dim3(8, 8, 1), 256, TG_SMEM>>>(
        p_y, p_outwTh, p_outwTh, p_outwTl, p_outwTl, nullptr, nullptr,
        out, 1024, 1024, 0, 0,
        nullptr, nullptr, nullptr, nullptr, nullptr, nullptr, nullptr, nullptr);
}

// round 16
// speedup vs baseline: 1.0461x; 1.0461x over previous
#include <cuda_runtime.h>
#include <cuda_bf16.h>
#include <cuda_fp16.h>
#include <math.h>
#include <stdint.h>

// ----------------------------- constants -----------------------------------
#define NSEQ   1024
#define DIM    1024
#define NH     16
#define NKH    4
#define NQH    4
#define DH     64
#define CBS    16
#define STRIDE 16
#define SBS    32
#define NSEL   8
#define NCB    64      // NSEQ/STRIDE
#define NFINE  32      // NCB/2
#define SCALE  0.125f

// ----------------------------- scratch -------------------------------------
__device__ float  g_q   [NH  * NSEQ * DH];
__device__ __half g_kh  [NKH * NSEQ * DH];
__device__ __half g_vh  [NKH * NSEQ * DH];
__device__ float  g_x   [2 * NKH * NCB * 1024];   // [k; v] MLP inputs
__device__ float  g_h   [2 * NKH * NCB * 1024];   // hidden
__device__ float  g_ckf [NKH * 65 * DH];
__device__ float  g_cvf [NKH * 65 * DH];
__device__ int    g_idx [NKH * NSEQ * NSEL];
__device__ float  g_cout[NH * NSEQ * DH];
__device__ float  g_y   [NSEQ * NH * DH];
__device__ float  g_gate[NSEQ * 2 * NH];
__device__ float  g_ct  [NSEQ * 32];
__device__ float  g_st  [NSEQ * 32];
// transposed weights, [N][K/2] packed bf16x2, hi/lo split
__device__ uint32_t g_wqkvTh[1536 * 512];
__device__ uint32_t g_wqkvTl[1536 * 512];
__device__ uint32_t g_kw1Th [1024 * 512];
__device__ uint32_t g_kw1Tl [1024 * 512];
__device__ uint32_t g_vw1Th [1024 * 512];
__device__ uint32_t g_vw1Tl [1024 * 512];
__device__ uint32_t g_outwTh[1024 * 512];
__device__ uint32_t g_outwTl[1024 * 512];

// ----------------------------- helpers --------------------------------------
__device__ __forceinline__ uint32_t packbf(float x, float y) {
    __nv_bfloat162 v;
    v.x = __float2bfloat16_rn(x);
    v.y = __float2bfloat16_rn(y);
    return *reinterpret_cast<uint32_t*>(&v);
}
__device__ __forceinline__ float bfres(float x) {
    return x - __bfloat162float(__float2bfloat16_rn(x));
}
__device__ __forceinline__ void mma_bf16(float* d,
                                         uint32_t a0, uint32_t a1, uint32_t a2, uint32_t a3,
                                         uint32_t b0, uint32_t b1) {
    asm volatile(
        "mma.sync.aligned.m16n8k16.row.col.f32.bf16.bf16.f32 "
        "{%0,%1,%2,%3}, {%4,%5,%6,%7}, {%8,%9}, {%0,%1,%2,%3};"
        : "+f"(d[0]), "+f"(d[1]), "+f"(d[2]), "+f"(d[3])
        : "r"(a0), "r"(a1), "r"(a2), "r"(a3), "r"(b0), "r"(b1));
}

// rope+scatter for one output pair (i = token, n = even qkv column)
__device__ __forceinline__ void qkv_scatter(
    int i, int n, float a, float b,
    const float* __restrict__ ct, const float* __restrict__ st,
    const float* __restrict__ kpos, const float* __restrict__ vpos,
    float* __restrict__ q, __half* __restrict__ kk,
    __half* __restrict__ vv, float* __restrict__ x)
{
    const int d = n & 63;
    if (n < 1280) {
        const int d2 = d >> 1;
        float cs = ct[i * 32 + d2];
        float sn = st[i * 32 + d2];
        float o1 = a * cs - b * sn;
        float o2 = b * cs + a * sn;
        if (n < 1024) {
            int h = n >> 6;
            *(float2*)&q[((size_t)h * NSEQ + i) * DH + d] = make_float2(o1, o2);
        } else {
            int kh = (n - 1024) >> 6;
            *(__half2*)&kk[((size_t)kh * NSEQ + i) * DH + d] = __floats2half2_rn(o1, o2);
            int blk = i >> 4, ci = i & 15;
            int pos = (kh * CBS + ci) * DH + d;
            float* xd = &x[(size_t)(kh * 64 + blk) * 1024 + ci * 64 + d];
            xd[0] = o1 + kpos[pos];
            xd[1] = o2 + kpos[pos + 1];
        }
    } else {
        int kh = (n - 1280) >> 6;
        *(__half2*)&vv[((size_t)kh * NSEQ + i) * DH + d] = __floats2half2_rn(a, b);
        int blk = i >> 4, ci = i & 15;
        int pos = (kh * CBS + ci) * DH + d;
        float* xd = &x[262144 + (size_t)(kh * 64 + blk) * 1024 + ci * 64 + d];
        xd[0] = a + vpos[pos];
        xd[1] = b + vpos[pos + 1];
    }
}

// --------- precision-split bf16 tensor-core GEMM (128x128 CTA tile) ---------
// QKV=1: epilogue fuses rope + q/k/v split + MLP-input build (C unused).
#define TG_RSTRIDE 20
#define TG_TILE_W  (128 * TG_RSTRIDE)
#define TG_BUF_W   (4 * TG_TILE_W)
#define TG_SMEM    (2 * TG_BUF_W * 4)
template<int ACT, int QKV>   // ACT: 0 none, 1 relu
__global__ __launch_bounds__(256)
void tgemm(const float* __restrict__ A,
           const uint32_t* __restrict__ BH0, const uint32_t* __restrict__ BH1,
           const uint32_t* __restrict__ BL0, const uint32_t* __restrict__ BL1,
           const float* __restrict__ bias0, const float* __restrict__ bias1,
           float* __restrict__ C, int Nc, int K, int bsA, int bsC,
           const float* __restrict__ ct, const float* __restrict__ st,
           const float* __restrict__ kpos, const float* __restrict__ vpos,
           float* __restrict__ qout, __half* __restrict__ kkout,
           __half* __restrict__ vvout, float* __restrict__ xout)
{
    extern __shared__ uint32_t smw[];
    const int z = blockIdx.z;
    const uint32_t* BH = z ? BH1 : BH0;
    const uint32_t* BL = z ? BL1 : BL0;
    const float* bias  = z ? bias1 : bias0;
    A += (size_t)z * bsA;
    C += (size_t)z * bsC;
    const int Kw = K >> 1;

    const int tid = threadIdx.x, wid = tid >> 5, lane = tid & 31;
    const int grp = lane >> 2, thr = lane & 3;
    const int wm = wid & 1, wn = wid >> 1;
    const int m0 = blockIdx.y * 128, n0 = blockIdx.x * 128;

    const int r0 = tid >> 3, c4 = tid & 7;
    const float*    Ap  = A  + (size_t)(m0 + r0) * K  + c4 * 4;
    const uint32_t* BHp = BH + (size_t)(n0 + r0) * Kw + c4 * 2;
    const uint32_t* BLp = BL + (size_t)(n0 + r0) * Kw + c4 * 2;

    float acc[4][4][4];
#pragma unroll
    for (int i = 0; i < 4; i++)
#pragma unroll
        for (int j = 0; j < 4; j++)
#pragma unroll
            for (int r = 0; r < 4; r++) acc[i][j][r] = 0.f;

    float4 av[4];
    uint2  bhv[4], blv[4];

#define STAGE(bufbase)                                                        \
    do {                                                                      \
        uint32_t* Ah = smw + (bufbase);                                       \
        uint32_t* Al = Ah + TG_TILE_W;                                        \
        uint32_t* Bh = Ah + 2 * TG_TILE_W;                                    \
        uint32_t* Bl = Ah + 3 * TG_TILE_W;                                    \
        _Pragma("unroll")                                                     \
        for (int j = 0; j < 4; j++) {                                         \
            int ro = (r0 + 32 * j) * TG_RSTRIDE + c4 * 2;                     \
            Ah[ro]     = packbf(av[j].x, av[j].y);                            \
            Ah[ro + 1] = packbf(av[j].z, av[j].w);                            \
            Al[ro]     = packbf(bfres(av[j].x), bfres(av[j].y));              \
            Al[ro + 1] = packbf(bfres(av[j].z), bfres(av[j].w));              \
            Bh[ro] = bhv[j].x; Bh[ro + 1] = bhv[j].y;                         \
            Bl[ro] = blv[j].x; Bl[ro + 1] = blv[j].y;                         \
        }                                                                     \
    } while (0)

#pragma unroll
    for (int j = 0; j < 4; j++) {
        av[j]  = *(const float4*)(Ap + (size_t)(32 * j) * K);
        bhv[j] = *(const uint2*)(BHp + (size_t)(32 * j) * Kw);
        blv[j] = *(const uint2*)(BLp + (size_t)(32 * j) * Kw);
    }
    STAGE(0);
    __syncthreads();

    const int nchunk = K >> 5;
    int cur = 0;
    for (int ch = 0; ch < nchunk; ch++) {
        const bool nxt = (ch + 1) < nchunk;
        if (nxt) {
            const int ko = (ch + 1) * 32, kw = (ch + 1) * 16;
#pragma unroll
            for (int j = 0; j < 4; j++) {
                av[j]  = *(const float4*)(Ap + (size_t)(32 * j) * K + ko);
                bhv[j] = *(const uint2*)(BHp + (size_t)(32 * j) * Kw + kw);
                blv[j] = *(const uint2*)(BLp + (size_t)(32 * j) * Kw + kw);
            }
        }
        const uint32_t* Ah = smw + cur * TG_BUF_W;
        const uint32_t* Al = Ah + TG_TILE_W;
        const uint32_t* Bh = Ah + 2 * TG_TILE_W;
        const uint32_t* Bl = Ah + 3 * TG_TILE_W;
#pragma unroll
        for (int ks = 0; ks < 2; ks++) {
            const int w0 = ks * 8;
            uint32_t ahf[4][4], alf[4][4], bhf[4][2], blf[4][2];
#pragma unroll
            for (int mt = 0; mt < 4; mt++) {
                const uint32_t* ap = Ah + (wm * 64 + mt * 16 + grp) * TG_RSTRIDE + w0 + thr;
                ahf[mt][0] = ap[0];
                ahf[mt][1] = ap[8 * TG_RSTRIDE];
                ahf[mt][2] = ap[4];
                ahf[mt][3] = ap[8 * TG_RSTRIDE + 4];
                const uint32_t* alp = Al + (wm * 64 + mt * 16 + grp) * TG_RSTRIDE + w0 + thr;
                alf[mt][0] = alp[0];
                alf[mt][1] = alp[8 * TG_RSTRIDE];
                alf[mt][2] = alp[4];
                alf[mt][3] = alp[8 * TG_RSTRIDE + 4];
            }
#pragma unroll
            for (int nt = 0; nt < 4; nt++) {
                const uint32_t* bp = Bh + (wn * 32 + nt * 8 + grp) * TG_RSTRIDE + w0 + thr;
                bhf[nt][0] = bp[0];
                bhf[nt][1] = bp[4];
                const uint32_t* blp = Bl + (wn * 32 + nt * 8 + grp) * TG_RSTRIDE + w0 + thr;
                blf[nt][0] = blp[0];
                blf[nt][1] = blp[4];
            }
#pragma unroll
            for (int mt = 0; mt < 4; mt++)
#pragma unroll
                for (int nt = 0; nt < 4; nt++) {
                    mma_bf16(acc[mt][nt], ahf[mt][0], ahf[mt][1], ahf[mt][2], ahf[mt][3],
                             bhf[nt][0], bhf[nt][1]);
                    mma_bf16(acc[mt][nt], ahf[mt][0], ahf[mt][1], ahf[mt][2], ahf[mt][3],
                             blf[nt][0], blf[nt][1]);
                    mma_bf16(acc[mt][nt], alf[mt][0], alf[mt][1], alf[mt][2], alf[mt][3],
                             bhf[nt][0], bhf[nt][1]);
                }
        }
        if (nxt) STAGE((cur ^ 1) * TG_BUF_W);
        __syncthreads();
        cur ^= 1;
    }
#undef STAGE

#pragma unroll
    for (int mt = 0; mt < 4; mt++) {
        const int m = m0 + wm * 64 + mt * 16 + grp;
#pragma unroll
        for (int nt = 0; nt < 4; nt++) {
            const int n = n0 + wn * 32 + nt * 8 + 2 * thr;
            if (QKV) {
                qkv_scatter(m,     n, acc[mt][nt][0], acc[mt][nt][1],
                            ct, st, kpos, vpos, qout, kkout, vvout, xout);
                qkv_scatter(m + 8, n, acc[mt][nt][2], acc[mt][nt][3],
                            ct, st, kpos, vpos, qout, kkout, vvout, xout);
            } else {
                float b0 = 0.f, b1 = 0.f;
                if (bias) { b0 = bias[n]; b1 = bias[n + 1]; }
                float v0 = acc[mt][nt][0] + b0;
                float v1 = acc[mt][nt][1] + b1;
                float v2 = acc[mt][nt][2] + b0;
                float v3 = acc[mt][nt][3] + b1;
                if (ACT == 1) {
                    v0 = fmaxf(v0, 0.f); v1 = fmaxf(v1, 0.f);
                    v2 = fmaxf(v2, 0.f); v3 = fmaxf(v3, 0.f);
                }
                *(float2*)(C + (size_t)m * Nc + n)       = make_float2(v0, v1);
                *(float2*)(C + (size_t)(m + 8) * Nc + n) = make_float2(v2, v3);
            }
        }
    }
}

// ---- fused weight transposes + bf16 hi/lo split + rope table (z==4) --------
__global__ void transpose_split_all(
    const float* __restrict__ s0, uint32_t* __restrict__ h0, uint32_t* __restrict__ l0,
    const float* __restrict__ s1, uint32_t* __restrict__ h1, uint32_t* __restrict__ l1,
    const float* __restrict__ s2, uint32_t* __restrict__ h2, uint32_t* __restrict__ l2,
    const float* __restrict__ s3, uint32_t* __restrict__ h3, uint32_t* __restrict__ l3,
    float* __restrict__ ct, float* __restrict__ st)
{
    const int z = blockIdx.z;
    const int tlin = threadIdx.y * 32 + threadIdx.x;
    if (z == 4) {
        int bidl = blockIdx.y * 48 + blockIdx.x;
        if (bidl >= 128) return;
        int id = bidl * 256 + tlin;
        int i = id >> 5, d2 = id & 31;
        double inv = exp((double)d2 * -0.28782313662425575);  // -ln(10000)/32
        double ang = (double)i * inv;
        double kq  = floor(ang * 0.15915494309189535);        // 1/(2*pi)
        float red  = (float)(ang - kq * 6.283185307179586);
        float sn, cs;
        sincosf(red, &sn, &cs);
        ct[id] = cs;
        st[id] = sn;
        return;
    }
    const float* src = (z == 0) ? s0 : (z == 1) ? s1 : (z == 2) ? s2 : s3;
    uint32_t* hi = (z == 0) ? h0 : (z == 1) ? h1 : (z == 2) ? h2 : h3;
    uint32_t* lo = (z == 0) ? l0 : (z == 1) ? l1 : (z == 2) ? l2 : l3;
    const int N = (z == 0) ? 1536 : 1024;
    const int K = 1024;
    if (blockIdx.x * 32 >= N) return;

    __shared__ float t[32][33];
    const int bx = blockIdx.x * 32, by = blockIdx.y * 32;
    const int tx = threadIdx.x, ty = threadIdx.y;
#pragma unroll
    for (int j = 0; j < 32; j += 8)
        t[ty + j][tx] = src[(size_t)(by + ty + j) * N + bx + tx];
    __syncthreads();
    const int Kw = K >> 1;
    if (tx < 16) {
#pragma unroll
        for (int jj = 0; jj < 4; jj++) {
            int n_l = ty + 8 * jj;
            float x0 = t[2 * tx][n_l];
            float x1 = t[2 * tx + 1][n_l];
            size_t o = (size_t)(bx + n_l) * Kw + (by >> 1) + tx;
            hi[o] = packbf(x0, x1);
            lo[o] = packbf(bfres(x0), bfres(x1));
        }
    }
}

// --------------- split-K skinny GEMM body (device function) ------------------
// KS-way K-split, RM rows per CTA, NC columns. RM*(NC/4)*KS == 256 threads.
// CKV=1: output row remapped to ckf/cvf layout (row + row/64 + 1).
template<int NC, int ACT, int CKV, int RM, int KS, int CHUNK>
__device__ __forceinline__ void skinny_body(
    const float* __restrict__ A, const float* __restrict__ B,
    const float* __restrict__ bias, float* __restrict__ C,
    int K, int bx, float* sm, int tid)
{
    constexpr int CG  = NC / 4;
    constexpr int TPS = 256 / KS;
    constexpr int AST = CHUNK + 4;
    float* As  = sm;                        // KS*RM*AST
    float* Bs  = As + KS * RM * AST;        // KS*CHUNK*NC
    float* red = Bs + KS * CHUNK * NC;      // KS*RM*NC

    const int ks  = tid / TPS;
    const int t   = tid % TPS;
    const int rr  = t / CG, cg = t % CG;
    const int r0  = bx * RM;
    const int ksl = K / KS;
    const int kbase = ks * ksl;

    float acc[4] = {0.f, 0.f, 0.f, 0.f};

    for (int c = 0; c < ksl; c += CHUNK) {
        for (int l = t; l < RM * (CHUNK / 4); l += TPS) {
            int row = l / (CHUNK / 4), c4 = (l % (CHUNK / 4)) * 4;
            *(float4*)&As[(ks * RM + row) * AST + c4] =
                *(const float4*)(A + (size_t)(r0 + row) * K + kbase + c + c4);
        }
        for (int l = t; l < CHUNK * CG; l += TPS) {
            int row = l / CG, c4 = (l % CG) * 4;
            *(float4*)&Bs[(ks * CHUNK + row) * NC + c4] =
                *(const float4*)(B + (size_t)(kbase + c + row) * NC + c4);
        }
        __syncthreads();
#pragma unroll
        for (int kk = 0; kk < CHUNK; kk++) {
            float a = As[(ks * RM + rr) * AST + kk];
            float4 b = *(const float4*)&Bs[(ks * CHUNK + kk) * NC + cg * 4];
            acc[0] += a * b.x;
            acc[1] += a * b.y;
            acc[2] += a * b.z;
            acc[3] += a * b.w;
        }
        __syncthreads();
    }

    *(float4*)&red[(ks * RM + rr) * NC + cg * 4] =
        make_float4(acc[0], acc[1], acc[2], acc[3]);
    __syncthreads();

    if (ks == 0) {
#pragma unroll
        for (int c4i = 0; c4i < 4; c4i++) {
            int col = cg * 4 + c4i;
            float v = 0.f;
#pragma unroll
            for (int s = 0; s < KS; s++) v += red[(s * RM + rr) * NC + col];
            if (bias) v += bias[col];
            if (ACT == 1) v = fmaxf(v, 0.f);
            if (ACT == 2) v = 1.f / (1.f + __expf(-v));
            int orow = r0 + rr;
            if (CKV) orow = orow + (orow >> 6) + 1;
            C[(size_t)orow * NC + col] = v;
        }
    }
}

// ------------- fused mlp2 (k,v) + gates dispatcher, one launch ---------------
// grid (128, 3): y=0 mlp2-k, y=1 mlp2-v, y=2 gates
__global__ __launch_bounds__(256)
void skinny_fused(const float* __restrict__ h,
                  const float* __restrict__ kc_w2, const float* __restrict__ vc_w2,
                  const float* __restrict__ kc_b2, const float* __restrict__ vc_b2,
                  const float* __restrict__ inp,
                  const float* __restrict__ gate_w, const float* __restrict__ gate_b,
                  float* __restrict__ ckf, float* __restrict__ cvf,
                  float* __restrict__ gate)
{
    // mlp2 body needs 8*2*20 + 8*16*64 + 8*2*64 = 9536 floats (38144 B)
    __shared__ float sm[9536];
    const int y = blockIdx.y;
    if (y < 2) {
        skinny_body<64, 0, 1, 2, 8, 16>(h + (size_t)y * 262144,
                                        y ? vc_w2 : kc_w2,
                                        y ? vc_b2 : kc_b2,
                                        y ? cvf : ckf,
                                        1024, blockIdx.x, sm, threadIdx.x);
    } else {
        skinny_body<32, 2, 0, 8, 4, 32>(inp, gate_w, gate_b, gate,
                                        1024, blockIdx.x, sm, threadIdx.x);
    }
}

// ------------------ coarse attention + fused top-k ---------------------------
__global__ __launch_bounds__(256)
void coarse_attn(const float* __restrict__ q, const float* __restrict__ ckf,
                 const float* __restrict__ cvf, const float* __restrict__ memkv,
                 float* __restrict__ cout, int* __restrict__ idx)
{
    __shared__ float s_ck[65 * 65];
    __shared__ float s_cv[65 * 64];
    __shared__ float s_imp[32 * 32];
    const int kh = blockIdx.y;
    const int q0 = blockIdx.x * 32;
    const int tid = threadIdx.x;
    for (int e = tid; e < 65 * 64; e += 256) {
        int j = e >> 6, d = e & 63;
        float ckv, cvv;
        if (j == 0) {
            ckv = memkv[kh * DH + d];
            cvv = memkv[NKH * DH + kh * DH + d];
        } else {
            ckv = ckf[kh * 65 * 64 + e];
            cvv = cvf[kh * 65 * 64 + e];
        }
        s_ck[j * 65 + d] = ckv;
        s_cv[e] = cvv;
    }
    for (int e = tid; e < 32 * 32; e += 256) s_imp[e] = 0.f;
    __syncthreads();

    const int warp = tid >> 5, lane = tid & 31;
    for (int unit = warp; unit < 128; unit += 8) {
        const int ql = unit >> 2;
        const int qh = unit & 3;
        const int qi = q0 + ql;
        const int h  = kh * NQH + qh;
        const float* qp = q + ((size_t)h * NSEQ + qi) * DH;
        const float qa = qp[lane], qb = qp[lane + 32];

        float s0 = 0.f, s1 = 0.f, s2 = 0.f;
#pragma unroll 8
        for (int d = 0; d < 32; d++) {
            float qd = __shfl_sync(0xffffffffu, qa, d);
            s0 += qd * s_ck[lane * 65 + d];
            s1 += qd * s_ck[(lane + 32) * 65 + d];
            s2 += qd * s_ck[64 * 65 + d];
        }
#pragma unroll 8
        for (int d = 0; d < 32; d++) {
            float qd = __shfl_sync(0xffffffffu, qb, d);
            s0 += qd * s_ck[lane * 65 + 32 + d];
            s1 += qd * s_ck[(lane + 32) * 65 + 32 + d];
            s2 += qd * s_ck[64 * 65 + 32 + d];
        }
        s0 *= SCALE; s1 *= SCALE; s2 *= SCALE;

        if (lane >= 1) atomicAdd(&s_imp[ql * 32 + ((lane - 1) >> 1)], s0);
        atomicAdd(&s_imp[ql * 32 + ((lane + 31) >> 1)], s1);
        if (lane == 0) atomicAdd(&s_imp[ql * 32 + 31], s2);

        float m = fmaxf(fmaxf(s0, s1), s2);
#pragma unroll
        for (int off = 16; off; off >>= 1)
            m = fmaxf(m, __shfl_xor_sync(0xffffffffu, m, off));
        float e0 = __expf(s0 - m);
        float e1 = __expf(s1 - m);
        float e2 = __expf(s2 - m);
        float den = e0 + e1;
#pragma unroll
        for (int off = 16; off; off >>= 1)
            den += __shfl_xor_sync(0xffffffffu, den, off);
        den += e2;

        float o0 = 0.f, o1 = 0.f;
#pragma unroll 8
        for (int j = 0; j < 32; j++) {
            float p = __shfl_sync(0xffffffffu, e0, j);
            o0 += p * s_cv[j * 64 + lane];
            o1 += p * s_cv[j * 64 + lane + 32];
        }
#pragma unroll 8
        for (int j = 0; j < 32; j++) {
            float p = __shfl_sync(0xffffffffu, e1, j);
            o0 += p * s_cv[(j + 32) * 64 + lane];
            o1 += p * s_cv[(j + 32) * 64 + lane + 32];
        }
        o0 += e2 * s_cv[64 * 64 + lane];
        o1 += e2 * s_cv[64 * 64 + lane + 32];

        float invd = 1.f / den;
        float* op = cout + ((size_t)h * NSEQ + qi) * DH;
        op[lane]      = o0 * invd;
        op[lane + 32] = o1 * invd;
    }
    __syncthreads();

    // fused top-8 per query (ranking invariant to the /8 scaling)
    for (int ql = warp; ql < 32; ql += 8) {
        float v = s_imp[ql * 32 + lane];
        int* od = idx + ((size_t)kh * NSEQ + q0 + ql) * NSEL;
        for (int s = 0; s < NSEL; s++) {
            float bv = v; int bi = lane;
#pragma unroll
            for (int off = 16; off; off >>= 1) {
                float ov = __shfl_xor_sync(0xffffffffu, bv, off);
                int   oi = __shfl_xor_sync(0xffffffffu, bi, off);
                if (ov > bv || (ov == bv && oi < bi)) { bv = ov; bi = oi; }
            }
            if (lane == 0) od[s] = bi;
            if (lane == bi) v = -INFINITY;
        }
    }
}

// --------- fine attention (fp16 K/V) + fused gated combine ------------------
// V chunk-0 gather issued BEFORE the softmax so its latency overlaps it.
__global__ __launch_bounds__(128)
void fine_attn(const float* __restrict__ q, const __half* __restrict__ kk,
               const __half* __restrict__ vv, const int* __restrict__ idx,
               const float* __restrict__ cout, const float* __restrict__ gate,
               float* __restrict__ y)
{
    __shared__ __half ks[128 * 66];
    __shared__ float qs[4 * 64];
    __shared__ float ssim[4 * 256];
    __shared__ float part[4][4][64];
    __shared__ float sden[4];
    __shared__ int   sidx[8];
    const int i = blockIdx.x, kh = blockIdx.y;
    const int tid = threadIdx.x, w = tid >> 5, lane = tid & 31;

    if (tid < 8) sidx[tid] = idx[((size_t)kh * NSEQ + i) * NSEL + tid];
    for (int t = tid; t < 256; t += 128) {
        int h = t >> 6, d = t & 63;
        qs[t] = q[((size_t)(kh * NQH + h) * NSEQ + i) * DH + d];
    }
    __syncthreads();

    const int row = w * 32 + lane;
    const __half2* ksh2 = (const __half2*)ks;
    const float2*  qs2  = (const float2*)qs;

    // Phase A: logits
    for (int c = 0; c < 2; c++) {
        for (int e = tid; e < 1024; e += 128) {
            int r = e >> 3, d8 = e & 7;
            int blk = sidx[c * 4 + (r >> 5)];
            uint4 kvv = *(const uint4*)&kk[(((size_t)kh * NSEQ) + blk * SBS + (r & 31)) * DH + d8 * 8];
            uint32_t* dst = (uint32_t*)&ks[r * 66 + d8 * 8];
            dst[0] = kvv.x; dst[1] = kvv.y; dst[2] = kvv.z; dst[3] = kvv.w;
        }
        __syncthreads();
        float s[4] = {0.f, 0.f, 0.f, 0.f};
#pragma unroll 4
        for (int d2 = 0; d2 < 32; d2++) {
            float2 kf = __half22float2(ksh2[row * 33 + d2]);
#pragma unroll
            for (int h = 0; h < 4; h++) {
                float2 qf = qs2[h * 32 + d2];
                s[h] += qf.x * kf.x + qf.y * kf.y;
            }
        }
#pragma unroll
        for (int h = 0; h < 4; h++)
            ssim[h * 256 + c * 128 + row] = s[h] * SCALE;
        __syncthreads();
    }

    // prefetch V chunk 0 into ks (free after phase A); softmax overlaps the loads
    for (int e = tid; e < 1024; e += 128) {
        int r = e >> 3, d8 = e & 7;
        int blk = sidx[(r >> 5)];
        uint4 vvv = *(const uint4*)&vv[(((size_t)kh * NSEQ) + blk * SBS + (r & 31)) * DH + d8 * 8];
        uint32_t* dst = (uint32_t*)&ks[r * 66 + d8 * 8];
        dst[0] = vvv.x; dst[1] = vvv.y; dst[2] = vvv.z; dst[3] = vvv.w;
    }

    // softmax: warp w handles head w (reads/writes ssim only — no ks conflict)
    float m = -INFINITY;
    for (int t = lane; t < 256; t += 32) m = fmaxf(m, ssim[w * 256 + t]);
#pragma unroll
    for (int off = 16; off; off >>= 1)
        m = fmaxf(m, __shfl_xor_sync(0xffffffffu, m, off));
    float s = 0.f;
    for (int t = lane; t < 256; t += 32) {
        float e = __expf(ssim[w * 256 + t] - m);
        ssim[w * 256 + t] = e;
        s += e;
    }
#pragma unroll
    for (int off = 16; off; off >>= 1)
        s += __shfl_xor_sync(0xffffffffu, s, off);
    if (lane == 0) sden[w] = s;
    __syncthreads();

    // Phase C: output (V0 already resident; load V1 between chunks)
    float o0[4] = {0.f, 0.f, 0.f, 0.f}, o1[4] = {0.f, 0.f, 0.f, 0.f};
    for (int c = 0; c < 2; c++) {
        if (c == 1) {
            for (int e = tid; e < 1024; e += 128) {
                int r = e >> 3, d8 = e & 7;
                int blk = sidx[4 + (r >> 5)];
                uint4 vvv = *(const uint4*)&vv[(((size_t)kh * NSEQ) + blk * SBS + (r & 31)) * DH + d8 * 8];
                uint32_t* dst = (uint32_t*)&ks[r * 66 + d8 * 8];
                dst[0] = vvv.x; dst[1] = vvv.y; dst[2] = vvv.z; dst[3] = vvv.w;
            }
            __syncthreads();
        }
#pragma unroll 4
        for (int jj = 0; jj < 32; jj++) {
            int r2 = w * 32 + jj;
            float v0 = __half2float(ks[r2 * 66 + lane]);
            float v1 = __half2float(ks[r2 * 66 + lane + 32]);
#pragma unroll
            for (int h = 0; h < 4; h++) {
                float p = ssim[h * 256 + c * 128 + r2];
                o0[h] += p * v0;
                o1[h] += p * v1;
            }
        }
        if (c == 0) __syncthreads();   // before V1 overwrites ks
    }

#pragma unroll
    for (int h = 0; h < 4; h++) {
        part[w][h][lane]      = o0[h];
        part[w][h][lane + 32] = o1[h];
    }
    __syncthreads();
    float r0 = part[0][w][lane] + part[1][w][lane] + part[2][w][lane] + part[3][w][lane];
    float r1 = part[0][w][lane + 32] + part[1][w][lane + 32] +
               part[2][w][lane + 32] + part[3][w][lane + 32];
    float invd = 1.f / sden[w];

    const int h = kh * NQH + w;
    float g0 = gate[i * 32 + 2 * h];
    float g1 = gate[i * 32 + 2 * h + 1];
    const float* cp = cout + ((size_t)h * NSEQ + i) * DH;
    float* op = y + (size_t)i * 1024 + h * 64;
    op[lane]      = g0 * cp[lane]      + g1 * (r0 * invd);
    op[lane + 32] = g0 * cp[lane + 32] + g1 * (r1 * invd);
}

// ----------------------------- launcher -------------------------------------
extern "C" void kernel_launch(void* const* d_in, const int* in_sizes, int n_in,
                              void* d_out, int out_size)
{
    const float* inp    = (const float*)d_in[0];
    const float* w_qkv  = (const float*)d_in[1];
    const float* k_pos  = (const float*)d_in[2];
    const float* v_pos  = (const float*)d_in[3];
    const float* mem_kv = (const float*)d_in[4];
    const float* kc_w1  = (const float*)d_in[5];
    const float* kc_b1  = (const float*)d_in[6];
    const float* kc_w2  = (const float*)d_in[7];
    const float* kc_b2  = (const float*)d_in[8];
    const float* vc_w1  = (const float*)d_in[9];
    const float* vc_b1  = (const float*)d_in[10];
    const float* vc_w2  = (const float*)d_in[11];
    const float* vc_b2  = (const float*)d_in[12];
    const float* gate_w = (const float*)d_in[13];
    const float* gate_b = (const float*)d_in[14];
    const float* out_w  = (const float*)d_in[15];
    float* out = (float*)d_out;

    float *p_q, *p_x, *p_h;
    float *p_ckf, *p_cvf, *p_cout, *p_y, *p_gate, *p_ct, *p_st;
    __half *p_kh, *p_vh;
    uint32_t *p_wqkvTh, *p_wqkvTl, *p_kw1Th, *p_kw1Tl, *p_vw1Th, *p_vw1Tl, *p_outwTh, *p_outwTl;
    int* p_idx;
    cudaGetSymbolAddress((void**)&p_q,    g_q);
    cudaGetSymbolAddress((void**)&p_kh,   g_kh);
    cudaGetSymbolAddress((void**)&p_vh,   g_vh);
    cudaGetSymbolAddress((void**)&p_x,    g_x);
    cudaGetSymbolAddress((void**)&p_h,    g_h);
    cudaGetSymbolAddress((void**)&p_ckf,  g_ckf);
    cudaGetSymbolAddress((void**)&p_cvf,  g_cvf);
    cudaGetSymbolAddress((void**)&p_idx,  g_idx);
    cudaGetSymbolAddress((void**)&p_cout, g_cout);
    cudaGetSymbolAddress((void**)&p_y,    g_y);
    cudaGetSymbolAddress((void**)&p_gate, g_gate);
    cudaGetSymbolAddress((void**)&p_ct,   g_ct);
    cudaGetSymbolAddress((void**)&p_st,   g_st);
    cudaGetSymbolAddress((void**)&p_wqkvTh, g_wqkvTh);
    cudaGetSymbolAddress((void**)&p_wqkvTl, g_wqkvTl);
    cudaGetSymbolAddress((void**)&p_kw1Th,  g_kw1Th);
    cudaGetSymbolAddress((void**)&p_kw1Tl,  g_kw1Tl);
    cudaGetSymbolAddress((void**)&p_vw1Th,  g_vw1Th);
    cudaGetSymbolAddress((void**)&p_vw1Tl,  g_vw1Tl);
    cudaGetSymbolAddress((void**)&p_outwTh, g_outwTh);
    cudaGetSymbolAddress((void**)&p_outwTl, g_outwTl);

    cudaFuncSetAttribute(tgemm<0, 0>, cudaFuncAttributeMaxDynamicSharedMemorySize, TG_SMEM);
    cudaFuncSetAttribute(tgemm<1, 0>, cudaFuncAttributeMaxDynamicSharedMemorySize, TG_SMEM);
    cudaFuncSetAttribute(tgemm<0, 1>, cudaFuncAttributeMaxDynamicSharedMemorySize, TG_SMEM);

    // 0) fused weight transposes + rope table (z==4)
    transpose_split_all<<<dim3(48, 32, 5), dim3(32, 8)>>>(
        w_qkv, p_wqkvTh, p_wqkvTl,
        kc_w1, p_kw1Th,  p_kw1Tl,
        vc_w1, p_vw1Th,  p_vw1Tl,
        out_w, p_outwTh, p_outwTl,
        p_ct, p_st);
    // 1) qkv projection with fused rope/split/x-build/fp16 epilogue
    tgemm<0, 1><<<dim3(12, 8, 1), 256, TG_SMEM>>>(
        inp, p_wqkvTh, p_wqkvTh, p_wqkvTl, p_wqkvTl, nullptr, nullptr,
        nullptr, 1536, 1024, 0, 0,
        p_ct, p_st, k_pos, v_pos, p_q, p_kh, p_vh, p_x);
    // 2) MLP layer 1 (relu), batched k/v
    tgemm<1, 0><<<dim3(8, 2, 2), 256, TG_SMEM>>>(
        p_x, p_kw1Th, p_vw1Th, p_kw1Tl, p_vw1Tl, kc_b1, vc_b1,
        p_h, 1024, 1024, 262144, 262144,
        nullptr, nullptr, nullptr, nullptr, nullptr, nullptr, nullptr, nullptr);
    // 3) fused MLP layer 2 (k,v) + gates, one launch (384 CTAs)
    skinny_fused<<<dim3(128, 3), 256>>>(p_h, kc_w2, vc_w2, kc_b2, vc_b2,
                                        inp, gate_w, gate_b,
                                        p_ckf, p_cvf, p_gate);
    // 4) coarse attention + importance + fused top-8
    coarse_attn<<<dim3(32, 4), 256>>>(p_q, p_ckf, p_cvf, mem_kv, p_cout, p_idx);
    // 5) fine attention (fp16 K/V) + fused gated combine -> y
    fine_attn<<<dim3(1024, 4), 128>>>(p_q, p_kh, p_vh, p_idx, p_cout, p_gate, p_y);
    // 6) output projection (bf16 3-term split)
    tgemm<0, 0><<<dim3(8, 8, 1), 256, TG_SMEM>>>(
        p_y, p_outwTh, p_outwTh, p_outwTl, p_outwTl, nullptr, nullptr,
        out, 1024, 1024, 0, 0,
        nullptr, nullptr, nullptr, nullptr, nullptr, nullptr, nullptr, nullptr);
}

// round 17
// speedup vs baseline: 1.0590x; 1.0123x over previous
#include <cuda_runtime.h>
#include <cuda_bf16.h>
#include <cuda_fp16.h>
#include <math.h>
#include <stdint.h>

// ----------------------------- constants -----------------------------------
#define NSEQ   1024
#define DIM    1024
#define NH     16
#define NKH    4
#define NQH    4
#define DH     64
#define CBS    16
#define STRIDE 16
#define SBS    32
#define NSEL   8
#define NCB    64      // NSEQ/STRIDE
#define NFINE  32      // NCB/2
#define SCALE  0.125f

// ----------------------------- scratch -------------------------------------
__device__ float  g_q   [NH  * NSEQ * DH];
__device__ __half g_kh  [NKH * NSEQ * DH];
__device__ __half g_vh  [NKH * NSEQ * DH];
__device__ float  g_x   [2 * NKH * NCB * 1024];   // [k; v] MLP inputs
__device__ float  g_h   [2 * NKH * NCB * 1024];   // hidden
__device__ float  g_ckf [NKH * 65 * DH];
__device__ float  g_cvf [NKH * 65 * DH];
__device__ int    g_idx [NKH * NSEQ * NSEL];
__device__ float  g_cout[NH * NSEQ * DH];
__device__ float  g_y   [NSEQ * NH * DH];
__device__ float  g_gate[NSEQ * 2 * NH];
__device__ float  g_ct  [NSEQ * 32];
__device__ float  g_st  [NSEQ * 32];
// transposed weights, [N][K/2] packed bf16x2, hi/lo split
__device__ uint32_t g_wqkvTh[1536 * 512];
__device__ uint32_t g_wqkvTl[1536 * 512];
__device__ uint32_t g_kw1Th [1024 * 512];
__device__ uint32_t g_kw1Tl [1024 * 512];
__device__ uint32_t g_vw1Th [1024 * 512];
__device__ uint32_t g_vw1Tl [1024 * 512];
__device__ uint32_t g_outwTh[1024 * 512];
__device__ uint32_t g_outwTl[1024 * 512];

// ----------------------------- helpers --------------------------------------
__device__ __forceinline__ uint32_t packbf(float x, float y) {
    __nv_bfloat162 v;
    v.x = __float2bfloat16_rn(x);
    v.y = __float2bfloat16_rn(y);
    return *reinterpret_cast<uint32_t*>(&v);
}
__device__ __forceinline__ float bfres(float x) {
    return x - __bfloat162float(__float2bfloat16_rn(x));
}
__device__ __forceinline__ void mma_bf16(float* d,
                                         uint32_t a0, uint32_t a1, uint32_t a2, uint32_t a3,
                                         uint32_t b0, uint32_t b1) {
    asm volatile(
        "mma.sync.aligned.m16n8k16.row.col.f32.bf16.bf16.f32 "
        "{%0,%1,%2,%3}, {%4,%5,%6,%7}, {%8,%9}, {%0,%1,%2,%3};"
        : "+f"(d[0]), "+f"(d[1]), "+f"(d[2]), "+f"(d[3])
        : "r"(a0), "r"(a1), "r"(a2), "r"(a3), "r"(b0), "r"(b1));
}

// rope+scatter for one output pair (i = token, n = even qkv column)
__device__ __forceinline__ void qkv_scatter(
    int i, int n, float a, float b,
    const float* __restrict__ ct, const float* __restrict__ st,
    const float* __restrict__ kpos, const float* __restrict__ vpos,
    float* __restrict__ q, __half* __restrict__ kk,
    __half* __restrict__ vv, float* __restrict__ x)
{
    const int d = n & 63;
    if (n < 1280) {
        const int d2 = d >> 1;
        float cs = ct[i * 32 + d2];
        float sn = st[i * 32 + d2];
        float o1 = a * cs - b * sn;
        float o2 = b * cs + a * sn;
        if (n < 1024) {
            int h = n >> 6;
            *(float2*)&q[((size_t)h * NSEQ + i) * DH + d] = make_float2(o1, o2);
        } else {
            int kh = (n - 1024) >> 6;
            *(__half2*)&kk[((size_t)kh * NSEQ + i) * DH + d] = __floats2half2_rn(o1, o2);
            int blk = i >> 4, ci = i & 15;
            int pos = (kh * CBS + ci) * DH + d;
            float* xd = &x[(size_t)(kh * 64 + blk) * 1024 + ci * 64 + d];
            xd[0] = o1 + kpos[pos];
            xd[1] = o2 + kpos[pos + 1];
        }
    } else {
        int kh = (n - 1280) >> 6;
        *(__half2*)&vv[((size_t)kh * NSEQ + i) * DH + d] = __floats2half2_rn(a, b);
        int blk = i >> 4, ci = i & 15;
        int pos = (kh * CBS + ci) * DH + d;
        float* xd = &x[262144 + (size_t)(kh * 64 + blk) * 1024 + ci * 64 + d];
        xd[0] = a + vpos[pos];
        xd[1] = b + vpos[pos + 1];
    }
}

// --------- precision-split bf16 tensor-core GEMM (128x128 CTA tile) ---------
// QKV=1: epilogue fuses rope + q/k/v split + MLP-input build (C unused).
#define TG_RSTRIDE 20
#define TG_TILE_W  (128 * TG_RSTRIDE)
#define TG_BUF_W   (4 * TG_TILE_W)
#define TG_SMEM    (2 * TG_BUF_W * 4)
template<int ACT, int QKV>   // ACT: 0 none, 1 relu
__global__ __launch_bounds__(256)
void tgemm(const float* __restrict__ A,
           const uint32_t* __restrict__ BH0, const uint32_t* __restrict__ BH1,
           const uint32_t* __restrict__ BL0, const uint32_t* __restrict__ BL1,
           const float* __restrict__ bias0, const float* __restrict__ bias1,
           float* __restrict__ C, int Nc, int K, int bsA, int bsC,
           const float* __restrict__ ct, const float* __restrict__ st,
           const float* __restrict__ kpos, const float* __restrict__ vpos,
           float* __restrict__ qout, __half* __restrict__ kkout,
           __half* __restrict__ vvout, float* __restrict__ xout)
{
    extern __shared__ uint32_t smw[];
    const int z = blockIdx.z;
    const uint32_t* BH = z ? BH1 : BH0;
    const uint32_t* BL = z ? BL1 : BL0;
    const float* bias  = z ? bias1 : bias0;
    A += (size_t)z * bsA;
    C += (size_t)z * bsC;
    const int Kw = K >> 1;

    const int tid = threadIdx.x, wid = tid >> 5, lane = tid & 31;
    const int grp = lane >> 2, thr = lane & 3;
    const int wm = wid & 1, wn = wid >> 1;
    const int m0 = blockIdx.y * 128, n0 = blockIdx.x * 128;

    const int r0 = tid >> 3, c4 = tid & 7;
    const float*    Ap  = A  + (size_t)(m0 + r0) * K  + c4 * 4;
    const uint32_t* BHp = BH + (size_t)(n0 + r0) * Kw + c4 * 2;
    const uint32_t* BLp = BL + (size_t)(n0 + r0) * Kw + c4 * 2;

    float acc[4][4][4];
#pragma unroll
    for (int i = 0; i < 4; i++)
#pragma unroll
        for (int j = 0; j < 4; j++)
#pragma unroll
            for (int r = 0; r < 4; r++) acc[i][j][r] = 0.f;

    float4 av[4];
    uint2  bhv[4], blv[4];

#define STAGE(bufbase)                                                        \
    do {                                                                      \
        uint32_t* Ah = smw + (bufbase);                                       \
        uint32_t* Al = Ah + TG_TILE_W;                                        \
        uint32_t* Bh = Ah + 2 * TG_TILE_W;                                    \
        uint32_t* Bl = Ah + 3 * TG_TILE_W;                                    \
        _Pragma("unroll")                                                     \
        for (int j = 0; j < 4; j++) {                                         \
            int ro = (r0 + 32 * j) * TG_RSTRIDE + c4 * 2;                     \
            Ah[ro]     = packbf(av[j].x, av[j].y);                            \
            Ah[ro + 1] = packbf(av[j].z, av[j].w);                            \
            Al[ro]     = packbf(bfres(av[j].x), bfres(av[j].y));              \
            Al[ro + 1] = packbf(bfres(av[j].z), bfres(av[j].w));              \
            Bh[ro] = bhv[j].x; Bh[ro + 1] = bhv[j].y;                         \
            Bl[ro] = blv[j].x; Bl[ro + 1] = blv[j].y;                         \
        }                                                                     \
    } while (0)

#pragma unroll
    for (int j = 0; j < 4; j++) {
        av[j]  = *(const float4*)(Ap + (size_t)(32 * j) * K);
        bhv[j] = *(const uint2*)(BHp + (size_t)(32 * j) * Kw);
        blv[j] = *(const uint2*)(BLp + (size_t)(32 * j) * Kw);
    }
    STAGE(0);
    __syncthreads();

    const int nchunk = K >> 5;
    int cur = 0;
    for (int ch = 0; ch < nchunk; ch++) {
        const bool nxt = (ch + 1) < nchunk;
        if (nxt) {
            const int ko = (ch + 1) * 32, kw = (ch + 1) * 16;
#pragma unroll
            for (int j = 0; j < 4; j++) {
                av[j]  = *(const float4*)(Ap + (size_t)(32 * j) * K + ko);
                bhv[j] = *(const uint2*)(BHp + (size_t)(32 * j) * Kw + kw);
                blv[j] = *(const uint2*)(BLp + (size_t)(32 * j) * Kw + kw);
            }
        }
        const uint32_t* Ah = smw + cur * TG_BUF_W;
        const uint32_t* Al = Ah + TG_TILE_W;
        const uint32_t* Bh = Ah + 2 * TG_TILE_W;
        const uint32_t* Bl = Ah + 3 * TG_TILE_W;
#pragma unroll
        for (int ks = 0; ks < 2; ks++) {
            const int w0 = ks * 8;
            uint32_t ahf[4][4], alf[4][4], bhf[4][2], blf[4][2];
#pragma unroll
            for (int mt = 0; mt < 4; mt++) {
                const uint32_t* ap = Ah + (wm * 64 + mt * 16 + grp) * TG_RSTRIDE + w0 + thr;
                ahf[mt][0] = ap[0];
                ahf[mt][1] = ap[8 * TG_RSTRIDE];
                ahf[mt][2] = ap[4];
                ahf[mt][3] = ap[8 * TG_RSTRIDE + 4];
                const uint32_t* alp = Al + (wm * 64 + mt * 16 + grp) * TG_RSTRIDE + w0 + thr;
                alf[mt][0] = alp[0];
                alf[mt][1] = alp[8 * TG_RSTRIDE];
                alf[mt][2] = alp[4];
                alf[mt][3] = alp[8 * TG_RSTRIDE + 4];
            }
#pragma unroll
            for (int nt = 0; nt < 4; nt++) {
                const uint32_t* bp = Bh + (wn * 32 + nt * 8 + grp) * TG_RSTRIDE + w0 + thr;
                bhf[nt][0] = bp[0];
                bhf[nt][1] = bp[4];
                const uint32_t* blp = Bl + (wn * 32 + nt * 8 + grp) * TG_RSTRIDE + w0 + thr;
                blf[nt][0] = blp[0];
                blf[nt][1] = blp[4];
            }
#pragma unroll
            for (int mt = 0; mt < 4; mt++)
#pragma unroll
                for (int nt = 0; nt < 4; nt++) {
                    mma_bf16(acc[mt][nt], ahf[mt][0], ahf[mt][1], ahf[mt][2], ahf[mt][3],
                             bhf[nt][0], bhf[nt][1]);
                    mma_bf16(acc[mt][nt], ahf[mt][0], ahf[mt][1], ahf[mt][2], ahf[mt][3],
                             blf[nt][0], blf[nt][1]);
                    mma_bf16(acc[mt][nt], alf[mt][0], alf[mt][1], alf[mt][2], alf[mt][3],
                             bhf[nt][0], bhf[nt][1]);
                }
        }
        if (nxt) STAGE((cur ^ 1) * TG_BUF_W);
        __syncthreads();
        cur ^= 1;
    }
#undef STAGE

#pragma unroll
    for (int mt = 0; mt < 4; mt++) {
        const int m = m0 + wm * 64 + mt * 16 + grp;
#pragma unroll
        for (int nt = 0; nt < 4; nt++) {
            const int n = n0 + wn * 32 + nt * 8 + 2 * thr;
            if (QKV) {
                qkv_scatter(m,     n, acc[mt][nt][0], acc[mt][nt][1],
                            ct, st, kpos, vpos, qout, kkout, vvout, xout);
                qkv_scatter(m + 8, n, acc[mt][nt][2], acc[mt][nt][3],
                            ct, st, kpos, vpos, qout, kkout, vvout, xout);
            } else {
                float b0 = 0.f, b1 = 0.f;
                if (bias) { b0 = bias[n]; b1 = bias[n + 1]; }
                float v0 = acc[mt][nt][0] + b0;
                float v1 = acc[mt][nt][1] + b1;
                float v2 = acc[mt][nt][2] + b0;
                float v3 = acc[mt][nt][3] + b1;
                if (ACT == 1) {
                    v0 = fmaxf(v0, 0.f); v1 = fmaxf(v1, 0.f);
                    v2 = fmaxf(v2, 0.f); v3 = fmaxf(v3, 0.f);
                }
                *(float2*)(C + (size_t)m * Nc + n)       = make_float2(v0, v1);
                *(float2*)(C + (size_t)(m + 8) * Nc + n) = make_float2(v2, v3);
            }
        }
    }
}

// ---- fused weight transposes + bf16 hi/lo split + rope table (z==4) --------
__global__ void transpose_split_all(
    const float* __restrict__ s0, uint32_t* __restrict__ h0, uint32_t* __restrict__ l0,
    const float* __restrict__ s1, uint32_t* __restrict__ h1, uint32_t* __restrict__ l1,
    const float* __restrict__ s2, uint32_t* __restrict__ h2, uint32_t* __restrict__ l2,
    const float* __restrict__ s3, uint32_t* __restrict__ h3, uint32_t* __restrict__ l3,
    float* __restrict__ ct, float* __restrict__ st)
{
    const int z = blockIdx.z;
    const int tlin = threadIdx.y * 32 + threadIdx.x;
    if (z == 4) {
        int bidl = blockIdx.y * 48 + blockIdx.x;
        if (bidl >= 128) return;
        int id = bidl * 256 + tlin;
        int i = id >> 5, d2 = id & 31;
        double inv = exp((double)d2 * -0.28782313662425575);  // -ln(10000)/32
        double ang = (double)i * inv;
        double kq  = floor(ang * 0.15915494309189535);        // 1/(2*pi)
        float red  = (float)(ang - kq * 6.283185307179586);
        float sn, cs;
        sincosf(red, &sn, &cs);
        ct[id] = cs;
        st[id] = sn;
        return;
    }
    const float* src = (z == 0) ? s0 : (z == 1) ? s1 : (z == 2) ? s2 : s3;
    uint32_t* hi = (z == 0) ? h0 : (z == 1) ? h1 : (z == 2) ? h2 : h3;
    uint32_t* lo = (z == 0) ? l0 : (z == 1) ? l1 : (z == 2) ? l2 : l3;
    const int N = (z == 0) ? 1536 : 1024;
    const int K = 1024;
    if (blockIdx.x * 32 >= N) return;

    __shared__ float t[32][33];
    const int bx = blockIdx.x * 32, by = blockIdx.y * 32;
    const int tx = threadIdx.x, ty = threadIdx.y;
#pragma unroll
    for (int j = 0; j < 32; j += 8)
        t[ty + j][tx] = src[(size_t)(by + ty + j) * N + bx + tx];
    __syncthreads();
    const int Kw = K >> 1;
    if (tx < 16) {
#pragma unroll
        for (int jj = 0; jj < 4; jj++) {
            int n_l = ty + 8 * jj;
            float x0 = t[2 * tx][n_l];
            float x1 = t[2 * tx + 1][n_l];
            size_t o = (size_t)(bx + n_l) * Kw + (by >> 1) + tx;
            hi[o] = packbf(x0, x1);
            lo[o] = packbf(bfres(x0), bfres(x1));
        }
    }
}

// --------- split-K skinny GEMM body, register double-buffered ----------------
// KS-way K-split, RM rows per CTA, NC columns. RM*(NC/4)*KS == 256 threads.
// Requires RM*(CHUNK/4) <= 256/KS (A loads fit one round).
// CKV=1: output row remapped to ckf/cvf layout (row + row/64 + 1).
template<int NC, int ACT, int CKV, int RM, int KS, int CHUNK>
__device__ __forceinline__ void skinny_body(
    const float* __restrict__ A, const float* __restrict__ B,
    const float* __restrict__ bias, float* __restrict__ C,
    int K, int bx, float* sm, int tid)
{
    constexpr int CG   = NC / 4;
    constexpr int TPS  = 256 / KS;
    constexpr int AST  = CHUNK + 4;
    constexpr int BPT  = (CHUNK * CG) / TPS;   // B float4 per thread
    constexpr int ANUM = RM * (CHUNK / 4);     // total A float4 (<= TPS)
    float* As  = sm;                        // KS*RM*AST
    float* Bs  = As + KS * RM * AST;        // KS*CHUNK*NC
    float* red = Bs + KS * CHUNK * NC;      // KS*RM*NC

    const int ks  = tid / TPS;
    const int t   = tid % TPS;
    const int rr  = t / CG, cg = t % CG;
    const int r0  = bx * RM;
    const int ksl = K / KS;
    const int kbase = ks * ksl;

    const bool hasA = (t < ANUM);
    const int arow = t / (CHUNK / 4), ac4 = (t % (CHUNK / 4)) * 4;

    float acc[4] = {0.f, 0.f, 0.f, 0.f};
    float4 aReg = make_float4(0.f, 0.f, 0.f, 0.f);
    float4 bReg[BPT];

    // prologue: load chunk 0 into registers
    if (hasA)
        aReg = *(const float4*)(A + (size_t)(r0 + arow) * K + kbase + ac4);
#pragma unroll
    for (int j = 0; j < BPT; j++) {
        int l = j * TPS + t;
        int row = l / CG, c4 = (l % CG) * 4;
        bReg[j] = *(const float4*)(B + (size_t)(kbase + row) * NC + c4);
    }

    for (int c = 0; c < ksl; c += CHUNK) {
        // store staged registers to smem
        if (hasA)
            *(float4*)&As[(ks * RM + arow) * AST + ac4] = aReg;
#pragma unroll
        for (int j = 0; j < BPT; j++) {
            int l = j * TPS + t;
            int row = l / CG, c4 = (l % CG) * 4;
            *(float4*)&Bs[(ks * CHUNK + row) * NC + c4] = bReg[j];
        }
        __syncthreads();
        // prefetch next chunk (overlaps compute below)
        if (c + CHUNK < ksl) {
            if (hasA)
                aReg = *(const float4*)(A + (size_t)(r0 + arow) * K +
                                        kbase + c + CHUNK + ac4);
#pragma unroll
            for (int j = 0; j < BPT; j++) {
                int l = j * TPS + t;
                int row = l / CG, c4 = (l % CG) * 4;
                bReg[j] = *(const float4*)(B + (size_t)(kbase + c + CHUNK + row) * NC + c4);
            }
        }
        // compute
#pragma unroll
        for (int kk = 0; kk < CHUNK; kk++) {
            float a = As[(ks * RM + rr) * AST + kk];
            float4 b = *(const float4*)&Bs[(ks * CHUNK + kk) * NC + cg * 4];
            acc[0] += a * b.x;
            acc[1] += a * b.y;
            acc[2] += a * b.z;
            acc[3] += a * b.w;
        }
        __syncthreads();
    }

    *(float4*)&red[(ks * RM + rr) * NC + cg * 4] =
        make_float4(acc[0], acc[1], acc[2], acc[3]);
    __syncthreads();

    if (ks == 0) {
#pragma unroll
        for (int c4i = 0; c4i < 4; c4i++) {
            int col = cg * 4 + c4i;
            float v = 0.f;
#pragma unroll
            for (int s = 0; s < KS; s++) v += red[(s * RM + rr) * NC + col];
            if (bias) v += bias[col];
            if (ACT == 1) v = fmaxf(v, 0.f);
            if (ACT == 2) v = 1.f / (1.f + __expf(-v));
            int orow = r0 + rr;
            if (CKV) orow = orow + (orow >> 6) + 1;
            C[(size_t)orow * NC + col] = v;
        }
    }
}

// ------------- fused mlp2 (k,v) + gates dispatcher, one launch ---------------
// grid (128, 3): y=0 mlp2-k, y=1 mlp2-v, y=2 gates
__global__ __launch_bounds__(256)
void skinny_fused(const float* __restrict__ h,
                  const float* __restrict__ kc_w2, const float* __restrict__ vc_w2,
                  const float* __restrict__ kc_b2, const float* __restrict__ vc_b2,
                  const float* __restrict__ inp,
                  const float* __restrict__ gate_w, const float* __restrict__ gate_b,
                  float* __restrict__ ckf, float* __restrict__ cvf,
                  float* __restrict__ gate)
{
    // mlp2 body needs 8*2*20 + 8*16*64 + 8*2*64 = 9536 floats (38144 B)
    __shared__ float sm[9536];
    const int y = blockIdx.y;
    if (y < 2) {
        skinny_body<64, 0, 1, 2, 8, 16>(h + (size_t)y * 262144,
                                        y ? vc_w2 : kc_w2,
                                        y ? vc_b2 : kc_b2,
                                        y ? cvf : ckf,
                                        1024, blockIdx.x, sm, threadIdx.x);
    } else {
        skinny_body<32, 2, 0, 8, 4, 32>(inp, gate_w, gate_b, gate,
                                        1024, blockIdx.x, sm, threadIdx.x);
    }
}

// ------------------ coarse attention + fused top-k ---------------------------
__global__ __launch_bounds__(256)
void coarse_attn(const float* __restrict__ q, const float* __restrict__ ckf,
                 const float* __restrict__ cvf, const float* __restrict__ memkv,
                 float* __restrict__ cout, int* __restrict__ idx)
{
    __shared__ float s_ck[65 * 65];
    __shared__ float s_cv[65 * 64];
    __shared__ float s_imp[32 * 32];
    const int kh = blockIdx.y;
    const int q0 = blockIdx.x * 32;
    const int tid = threadIdx.x;
    for (int e = tid; e < 65 * 64; e += 256) {
        int j = e >> 6, d = e & 63;
        float ckv, cvv;
        if (j == 0) {
            ckv = memkv[kh * DH + d];
            cvv = memkv[NKH * DH + kh * DH + d];
        } else {
            ckv = ckf[kh * 65 * 64 + e];
            cvv = cvf[kh * 65 * 64 + e];
        }
        s_ck[j * 65 + d] = ckv;
        s_cv[e] = cvv;
    }
    for (int e = tid; e < 32 * 32; e += 256) s_imp[e] = 0.f;
    __syncthreads();

    const int warp = tid >> 5, lane = tid & 31;
    for (int unit = warp; unit < 128; unit += 8) {
        const int ql = unit >> 2;
        const int qh = unit & 3;
        const int qi = q0 + ql;
        const int h  = kh * NQH + qh;
        const float* qp = q + ((size_t)h * NSEQ + qi) * DH;
        const float qa = qp[lane], qb = qp[lane + 32];

        float s0 = 0.f, s1 = 0.f, s2 = 0.f;
#pragma unroll 8
        for (int d = 0; d < 32; d++) {
            float qd = __shfl_sync(0xffffffffu, qa, d);
            s0 += qd * s_ck[lane * 65 + d];
            s1 += qd * s_ck[(lane + 32) * 65 + d];
            s2 += qd * s_ck[64 * 65 + d];
        }
#pragma unroll 8
        for (int d = 0; d < 32; d++) {
            float qd = __shfl_sync(0xffffffffu, qb, d);
            s0 += qd * s_ck[lane * 65 + 32 + d];
            s1 += qd * s_ck[(lane + 32) * 65 + 32 + d];
            s2 += qd * s_ck[64 * 65 + 32 + d];
        }
        s0 *= SCALE; s1 *= SCALE; s2 *= SCALE;

        if (lane >= 1) atomicAdd(&s_imp[ql * 32 + ((lane - 1) >> 1)], s0);
        atomicAdd(&s_imp[ql * 32 + ((lane + 31) >> 1)], s1);
        if (lane == 0) atomicAdd(&s_imp[ql * 32 + 31], s2);

        float m = fmaxf(fmaxf(s0, s1), s2);
#pragma unroll
        for (int off = 16; off; off >>= 1)
            m = fmaxf(m, __shfl_xor_sync(0xffffffffu, m, off));
        float e0 = __expf(s0 - m);
        float e1 = __expf(s1 - m);
        float e2 = __expf(s2 - m);
        float den = e0 + e1;
#pragma unroll
        for (int off = 16; off; off >>= 1)
            den += __shfl_xor_sync(0xffffffffu, den, off);
        den += e2;

        float o0 = 0.f, o1 = 0.f;
#pragma unroll 8
        for (int j = 0; j < 32; j++) {
            float p = __shfl_sync(0xffffffffu, e0, j);
            o0 += p * s_cv[j * 64 + lane];
            o1 += p * s_cv[j * 64 + lane + 32];
        }
#pragma unroll 8
        for (int j = 0; j < 32; j++) {
            float p = __shfl_sync(0xffffffffu, e1, j);
            o0 += p * s_cv[(j + 32) * 64 + lane];
            o1 += p * s_cv[(j + 32) * 64 + lane + 32];
        }
        o0 += e2 * s_cv[64 * 64 + lane];
        o1 += e2 * s_cv[64 * 64 + lane + 32];

        float invd = 1.f / den;
        float* op = cout + ((size_t)h * NSEQ + qi) * DH;
        op[lane]      = o0 * invd;
        op[lane + 32] = o1 * invd;
    }
    __syncthreads();

    // fused top-8 per query (ranking invariant to the /8 scaling)
    for (int ql = warp; ql < 32; ql += 8) {
        float v = s_imp[ql * 32 + lane];
        int* od = idx + ((size_t)kh * NSEQ + q0 + ql) * NSEL;
        for (int s = 0; s < NSEL; s++) {
            float bv = v; int bi = lane;
#pragma unroll
            for (int off = 16; off; off >>= 1) {
                float ov = __shfl_xor_sync(0xffffffffu, bv, off);
                int   oi = __shfl_xor_sync(0xffffffffu, bi, off);
                if (ov > bv || (ov == bv && oi < bi)) { bv = ov; bi = oi; }
            }
            if (lane == 0) od[s] = bi;
            if (lane == bi) v = -INFINITY;
        }
    }
}

// --------- fine attention (fp16 K/V) + fused gated combine ------------------
__global__ __launch_bounds__(128)
void fine_attn(const float* __restrict__ q, const __half* __restrict__ kk,
               const __half* __restrict__ vv, const int* __restrict__ idx,
               const float* __restrict__ cout, const float* __restrict__ gate,
               float* __restrict__ y)
{
    __shared__ __half ks[128 * 66];
    __shared__ float qs[4 * 64];
    __shared__ float ssim[4 * 256];
    __shared__ float part[4][4][64];
    __shared__ float sden[4];
    __shared__ int   sidx[8];
    const int i = blockIdx.x, kh = blockIdx.y;
    const int tid = threadIdx.x, w = tid >> 5, lane = tid & 31;

    if (tid < 8) sidx[tid] = idx[((size_t)kh * NSEQ + i) * NSEL + tid];
    for (int t = tid; t < 256; t += 128) {
        int h = t >> 6, d = t & 63;
        qs[t] = q[((size_t)(kh * NQH + h) * NSEQ + i) * DH + d];
    }
    __syncthreads();

    const int row = w * 32 + lane;
    const __half2* ksh2 = (const __half2*)ks;
    const float2*  qs2  = (const float2*)qs;

    for (int c = 0; c < 2; c++) {
        for (int e = tid; e < 1024; e += 128) {
            int r = e >> 3, d8 = e & 7;
            int blk = sidx[c * 4 + (r >> 5)];
            uint4 kvv = *(const uint4*)&kk[(((size_t)kh * NSEQ) + blk * SBS + (r & 31)) * DH + d8 * 8];
            uint32_t* dst = (uint32_t*)&ks[r * 66 + d8 * 8];
            dst[0] = kvv.x; dst[1] = kvv.y; dst[2] = kvv.z; dst[3] = kvv.w;
        }
        __syncthreads();
        float s[4] = {0.f, 0.f, 0.f, 0.f};
#pragma unroll 4
        for (int d2 = 0; d2 < 32; d2++) {
            float2 kf = __half22float2(ksh2[row * 33 + d2]);
#pragma unroll
            for (int h = 0; h < 4; h++) {
                float2 qf = qs2[h * 32 + d2];
                s[h] += qf.x * kf.x + qf.y * kf.y;
            }
        }
#pragma unroll
        for (int h = 0; h < 4; h++)
            ssim[h * 256 + c * 128 + row] = s[h] * SCALE;
        __syncthreads();
    }

    float m = -INFINITY;
    for (int t = lane; t < 256; t += 32) m = fmaxf(m, ssim[w * 256 + t]);
#pragma unroll
    for (int off = 16; off; off >>= 1)
        m = fmaxf(m, __shfl_xor_sync(0xffffffffu, m, off));
    float s = 0.f;
    for (int t = lane; t < 256; t += 32) {
        float e = __expf(ssim[w * 256 + t] - m);
        ssim[w * 256 + t] = e;
        s += e;
    }
#pragma unroll
    for (int off = 16; off; off >>= 1)
        s += __shfl_xor_sync(0xffffffffu, s, off);
    if (lane == 0) sden[w] = s;
    __syncthreads();

    float o0[4] = {0.f, 0.f, 0.f, 0.f}, o1[4] = {0.f, 0.f, 0.f, 0.f};
    for (int c = 0; c < 2; c++) {
        for (int e = tid; e < 1024; e += 128) {
            int r = e >> 3, d8 = e & 7;
            int blk = sidx[c * 4 + (r >> 5)];
            uint4 vvv = *(const uint4*)&vv[(((size_t)kh * NSEQ) + blk * SBS + (r & 31)) * DH + d8 * 8];
            uint32_t* dst = (uint32_t*)&ks[r * 66 + d8 * 8];
            dst[0] = vvv.x; dst[1] = vvv.y; dst[2] = vvv.z; dst[3] = vvv.w;
        }
        __syncthreads();
#pragma unroll 4
        for (int jj = 0; jj < 32; jj++) {
            int r2 = w * 32 + jj;
            float v0 = __half2float(ks[r2 * 66 + lane]);
            float v1 = __half2float(ks[r2 * 66 + lane + 32]);
#pragma unroll
            for (int h = 0; h < 4; h++) {
                float p = ssim[h * 256 + c * 128 + r2];
                o0[h] += p * v0;
                o1[h] += p * v1;
            }
        }
        __syncthreads();
    }

#pragma unroll
    for (int h = 0; h < 4; h++) {
        part[w][h][lane]      = o0[h];
        part[w][h][lane + 32] = o1[h];
    }
    __syncthreads();
    float r0 = part[0][w][lane] + part[1][w][lane] + part[2][w][lane] + part[3][w][lane];
    float r1 = part[0][w][lane + 32] + part[1][w][lane + 32] +
               part[2][w][lane + 32] + part[3][w][lane + 32];
    float invd = 1.f / sden[w];

    const int h = kh * NQH + w;
    float g0 = gate[i * 32 + 2 * h];
    float g1 = gate[i * 32 + 2 * h + 1];
    const float* cp = cout + ((size_t)h * NSEQ + i) * DH;
    float* op = y + (size_t)i * 1024 + h * 64;
    op[lane]      = g0 * cp[lane]      + g1 * (r0 * invd);
    op[lane + 32] = g0 * cp[lane + 32] + g1 * (r1 * invd);
}

// ----------------------------- launcher -------------------------------------
extern "C" void kernel_launch(void* const* d_in, const int* in_sizes, int n_in,
                              void* d_out, int out_size)
{
    const float* inp    = (const float*)d_in[0];
    const float* w_qkv  = (const float*)d_in[1];
    const float* k_pos  = (const float*)d_in[2];
    const float* v_pos  = (const float*)d_in[3];
    const float* mem_kv = (const float*)d_in[4];
    const float* kc_w1  = (const float*)d_in[5];
    const float* kc_b1  = (const float*)d_in[6];
    const float* kc_w2  = (const float*)d_in[7];
    const float* kc_b2  = (const float*)d_in[8];
    const float* vc_w1  = (const float*)d_in[9];
    const float* vc_b1  = (const float*)d_in[10];
    const float* vc_w2  = (const float*)d_in[11];
    const float* vc_b2  = (const float*)d_in[12];
    const float* gate_w = (const float*)d_in[13];
    const float* gate_b = (const float*)d_in[14];
    const float* out_w  = (const float*)d_in[15];
    float* out = (float*)d_out;

    float *p_q, *p_x, *p_h;
    float *p_ckf, *p_cvf, *p_cout, *p_y, *p_gate, *p_ct, *p_st;
    __half *p_kh, *p_vh;
    uint32_t *p_wqkvTh, *p_wqkvTl, *p_kw1Th, *p_kw1Tl, *p_vw1Th, *p_vw1Tl, *p_outwTh, *p_outwTl;
    int* p_idx;
    cudaGetSymbolAddress((void**)&p_q,    g_q);
    cudaGetSymbolAddress((void**)&p_kh,   g_kh);
    cudaGetSymbolAddress((void**)&p_vh,   g_vh);
    cudaGetSymbolAddress((void**)&p_x,    g_x);
    cudaGetSymbolAddress((void**)&p_h,    g_h);
    cudaGetSymbolAddress((void**)&p_ckf,  g_ckf);
    cudaGetSymbolAddress((void**)&p_cvf,  g_cvf);
    cudaGetSymbolAddress((void**)&p_idx,  g_idx);
    cudaGetSymbolAddress((void**)&p_cout, g_cout);
    cudaGetSymbolAddress((void**)&p_y,    g_y);
    cudaGetSymbolAddress((void**)&p_gate, g_gate);
    cudaGetSymbolAddress((void**)&p_ct,   g_ct);
    cudaGetSymbolAddress((void**)&p_st,   g_st);
    cudaGetSymbolAddress((void**)&p_wqkvTh, g_wqkvTh);
    cudaGetSymbolAddress((void**)&p_wqkvTl, g_wqkvTl);
    cudaGetSymbolAddress((void**)&p_kw1Th,  g_kw1Th);
    cudaGetSymbolAddress((void**)&p_kw1Tl,  g_kw1Tl);
    cudaGetSymbolAddress((void**)&p_vw1Th,  g_vw1Th);
    cudaGetSymbolAddress((void**)&p_vw1Tl,  g_vw1Tl);
    cudaGetSymbolAddress((void**)&p_outwTh, g_outwTh);
    cudaGetSymbolAddress((void**)&p_outwTl, g_outwTl);

    cudaFuncSetAttribute(tgemm<0, 0>, cudaFuncAttributeMaxDynamicSharedMemorySize, TG_SMEM);
    cudaFuncSetAttribute(tgemm<1, 0>, cudaFuncAttributeMaxDynamicSharedMemorySize, TG_SMEM);
    cudaFuncSetAttribute(tgemm<0, 1>, cudaFuncAttributeMaxDynamicSharedMemorySize, TG_SMEM);

    // 0) fused weight transposes + rope table (z==4)
    transpose_split_all<<<dim3(48, 32, 5), dim3(32, 8)>>>(
        w_qkv, p_wqkvTh, p_wqkvTl,
        kc_w1, p_kw1Th,  p_kw1Tl,
        vc_w1, p_vw1Th,  p_vw1Tl,
        out_w, p_outwTh, p_outwTl,
        p_ct, p_st);
    // 1) qkv projection with fused rope/split/x-build/fp16 epilogue
    tgemm<0, 1><<<dim3(12, 8, 1), 256, TG_SMEM>>>(
        inp, p_wqkvTh, p_wqkvTh, p_wqkvTl, p_wqkvTl, nullptr, nullptr,
        nullptr, 1536, 1024, 0, 0,
        p_ct, p_st, k_pos, v_pos, p_q, p_kh, p_vh, p_x);
    // 2) MLP layer 1 (relu), batched k/v
    tgemm<1, 0><<<dim3(8, 2, 2), 256, TG_SMEM>>>(
        p_x, p_kw1Th, p_vw1Th, p_kw1Tl, p_vw1Tl, kc_b1, vc_b1,
        p_h, 1024, 1024, 262144, 262144,
        nullptr, nullptr, nullptr, nullptr, nullptr, nullptr, nullptr, nullptr);
    // 3) fused MLP layer 2 (k,v) + gates, one launch (384 CTAs)
    skinny_fused<<<dim3(128, 3), 256>>>(p_h, kc_w2, vc_w2, kc_b2, vc_b2,
                                        inp, gate_w, gate_b,
                                        p_ckf, p_cvf, p_gate);
    // 4) coarse attention + importance + fused top-8
    coarse_attn<<<dim3(32, 4), 256>>>(p_q, p_ckf, p_cvf, mem_kv, p_cout, p_idx);
    // 5) fine attention (fp16 K/V) + fused gated combine -> y
    fine_attn<<<dim3(1024, 4), 128>>>(p_q, p_kh, p_vh, p_idx, p_cout, p_gate, p_y);
    // 6) output projection (bf16 3-term split)
    tgemm<0, 0><<<dim3(8, 8, 1), 256, TG_SMEM>>>(
        p_y, p_outwTh, p_outwTh, p_outwTl, p_outwTl, nullptr, nullptr,
        out, 1024, 1024, 0, 0,
        nullptr, nullptr, nullptr, nullptr, nullptr, nullptr, nullptr, nullptr);
}